// round 9
// baseline (speedup 1.0000x reference)
#include <cuda_runtime.h>
#include <cuda_bf16.h>

// ---------------------------------------------------------------------------
// CGCNN: B=16, N=1024, M=12, F=64, BF=128, N_CONV=3, VOCAB=100
// total@W = x@W1 + gather(x@W2) + bond@W3 ; proj fused into conv/embed.
// Bond GEMM on tensor cores via mma.sync m16n8k16 bf16 (sm_103-safe PTX),
// hi/lo split fp32-accurate: bh*Wh + bh*Wl + bl*Wh (lo*lo dropped, ~2^-18).
// ---------------------------------------------------------------------------

#define BN_ALPHA 0.99950037f   // 1/sqrt(1+1e-3)

__device__ float g_X0[16 * 1024 * 64];
__device__ float g_X1[16 * 1024 * 64];
__device__ float g_Y1[2][16 * 1024 * 64];
__device__ float g_Y2[2][16 * 1024 * 64];
__device__ float g_S1[2][16 * 1024];
__device__ float g_S2[2][16 * 1024];
__device__ __nv_bfloat16 g_WA[3][2 * 64 * 136];          // WT [hi|lo], n-major
__device__ __nv_bfloat16 g_BB[1024ull * 2 * 192 * 136];  // bond [hi|lo]/tile

// ---- mbarrier / bulk helpers ----------------------------------------------
__device__ __forceinline__ void mbar_init(unsigned m, unsigned c) {
    asm volatile("mbarrier.init.shared.b64 [%0], %1;" ::"r"(m), "r"(c)
                 : "memory");
}
__device__ __forceinline__ void mbar_expect(unsigned m, unsigned b) {
    asm volatile("mbarrier.arrive.expect_tx.shared.b64 _, [%0], %1;" ::"r"(m),
                 "r"(b)
                 : "memory");
}
__device__ __forceinline__ void mbar_wait(unsigned m) {
    asm volatile(
        "{\n\t.reg .pred P;\n\tW%=:\n\t"
        "mbarrier.try_wait.parity.acquire.cta.shared::cta.b64 P, [%0], 0;\n\t"
        "@!P bra W%=;\n\t}" ::"r"(m)
        : "memory");
}
__device__ __forceinline__ void bulk_cp(unsigned d, const void* s, unsigned b,
                                        unsigned m) {
    asm volatile(
        "cp.async.bulk.shared::cta.global.mbarrier::complete_tx::bytes "
        "[%0], [%1], %2, [%3];" ::"r"(d),
        "l"(s), "r"(b), "r"(m)
        : "memory");
}

// ---- tensor-core helpers (sm_80+ PTX, safe on sm_103) ---------------------
__device__ __forceinline__ void mma16816(float* d, const unsigned* a,
                                         const unsigned* b) {
    asm volatile(
        "mma.sync.aligned.m16n8k16.row.col.f32.bf16.bf16.f32 "
        "{%0,%1,%2,%3}, {%4,%5,%6,%7}, {%8,%9}, {%0,%1,%2,%3};"
        : "+f"(d[0]), "+f"(d[1]), "+f"(d[2]), "+f"(d[3])
        : "r"(a[0]), "r"(a[1]), "r"(a[2]), "r"(a[3]), "r"(b[0]), "r"(b[1]));
}
__device__ __forceinline__ void ldmx4(unsigned* a, unsigned addr) {
    asm volatile(
        "ldmatrix.sync.aligned.m8n8.x4.shared.b16 {%0,%1,%2,%3}, [%4];"
        : "=r"(a[0]), "=r"(a[1]), "=r"(a[2]), "=r"(a[3])
        : "r"(addr));
}
__device__ __forceinline__ float2 bf2(unsigned u) {
    __nv_bfloat162 h = reinterpret_cast<__nv_bfloat162&>(u);
    return __bfloat1622float2(h);
}

// ---------------------------------------------------------------------------
// prep_w_k: WT[n][k] bf16 hi/lo, rows padded to 136. grid 3 x 256.
// ---------------------------------------------------------------------------
__global__ void __launch_bounds__(256) prep_w_k(const float* __restrict__ cw) {
    int l = blockIdx.x;
    const float* W = cw + l * 256 * 64 + 128 * 64;   // [k][n]
    for (int t = threadIdx.x; t < 8192; t += 256) {
        int n = t >> 7, k = t & 127;
        float wv = W[k * 64 + n];
        __nv_bfloat16 h = __float2bfloat16(wv);
        g_WA[l][n * 136 + k] = h;
        g_WA[l][8704 + n * 136 + k] =
            __float2bfloat16(wv - __bfloat162float(h));
    }
}

// ---------------------------------------------------------------------------
// prep_bond_k: per 16-atom tile (192 rows) emit [hi 192x136 | lo 192x136]
// bf16 row-major. grid 1024 x 384 (thread = row x 64-col half).
// ---------------------------------------------------------------------------
__global__ void __launch_bounds__(384) prep_bond_k(
    const float* __restrict__ bond) {
    size_t tile = blockIdx.x;
    int t = threadIdx.x;
    int r = t >> 1, ac = t & 1;
    const float* src = bond + (tile * 192 + r) * 128 + ac * 64;
    __nv_bfloat16* dh = g_BB + tile * 52224 + r * 136 + ac * 64;
    __nv_bfloat16* dl = dh + 26112;
#pragma unroll 4
    for (int j = 0; j < 64; j += 2) {
        float2 v = *(const float2*)(src + j);
        __nv_bfloat16 h0 = __float2bfloat16(v.x);
        __nv_bfloat16 h1 = __float2bfloat16(v.y);
        __nv_bfloat162 hh, ll;
        hh.x = h0;
        hh.y = h1;
        ll.x = __float2bfloat16(v.x - __bfloat162float(h0));
        ll.y = __float2bfloat16(v.y - __bfloat162float(h1));
        *(__nv_bfloat162*)(dh + j) = hh;
        *(__nv_bfloat162*)(dl + j) = ll;
    }
}

// ---------------------------------------------------------------------------
// proj8 + embed (exact fp32, unchanged)
// ---------------------------------------------------------------------------
__device__ __forceinline__ void proj8(const float* __restrict__ xs, int bn0,
                                      int r0, int c2, int yb,
                                      const float* __restrict__ cwn,
                                      const float* __restrict__ fwn) {
    const float* wp;
    int st;
    if (c2 < 64) {
        wp = cwn + c2;
        st = 64;
    } else if (c2 < 128) {
        wp = cwn + 64 * 64 + (c2 - 64);
        st = 64;
    } else {
        wp = fwn + (c2 - 128) * 64;
        st = 1;
    }
    float acc[8] = {0.f, 0.f, 0.f, 0.f, 0.f, 0.f, 0.f, 0.f};
#pragma unroll 8
    for (int k = 0; k < 64; k++) {
        float wv = __ldg(wp + k * st);
#pragma unroll
        for (int rr = 0; rr < 8; rr++) acc[rr] += xs[(r0 + rr) * 68 + k] * wv;
    }
    if (c2 < 64) {
#pragma unroll
        for (int rr = 0; rr < 8; rr++)
            g_Y1[yb][(bn0 + r0 + rr) * 64 + c2] = acc[rr];
    } else if (c2 < 128) {
#pragma unroll
        for (int rr = 0; rr < 8; rr++)
            g_Y2[yb][(bn0 + r0 + rr) * 64 + (c2 - 64)] = acc[rr];
    } else if (c2 == 128) {
#pragma unroll
        for (int rr = 0; rr < 8; rr++) g_S1[yb][bn0 + r0 + rr] = acc[rr];
    } else {
#pragma unroll
        for (int rr = 0; rr < 8; rr++) g_S2[yb][bn0 + r0 + rr] = acc[rr];
    }
}

__global__ void __launch_bounds__(256) embed_proj_k(
    const int* __restrict__ types, const float* __restrict__ emb,
    const float* __restrict__ cwn, const float* __restrict__ fwn) {
    __shared__ float xs[16 * 68];
    int tid = threadIdx.x;
    int bn0 = blockIdx.x * 16;
    {
        int r = tid >> 4, q = tid & 15;
        int t = types[bn0 + r];
        float4 v = *(const float4*)(emb + t * 64 + q * 4);
        *(float4*)(xs + r * 68 + q * 4) = v;
        *(float4*)(g_X0 + (bn0 + r) * 64 + q * 4) = v;
    }
    __syncthreads();
    if (tid < 130) {
        proj8(xs, bn0, 0, tid, 0, cwn, fwn);
        proj8(xs, bn0, 8, tid, 0, cwn, fwn);
    }
}

// ---------------------------------------------------------------------------
// conv_k: one block = 16 atoms (192 rows), 512 threads, 16 warps = 4x4 grid
// (M tile 48, N tile 16). 3 mma passes: bh*Wh + bh*Wl + bl*Wh.
// smem map (bytes): 16,24 mbars | 1024 sBh(52224) | 53248 sBl(52224) |
// 105472 sWh(17408) | 122880 sWl(17408) | 140288 fs | 140800 ft | 141568 nb |
// 142336 xb | 146688 pb | 147968 y1s(4096) -> 152064
// reuse after GEMM: y2s = sBh region, Cs = sBl region.
// ---------------------------------------------------------------------------
#define CONV_SMEM 152064

__global__ void __launch_bounds__(512, 1) conv_k(
    int l, int flip, int yrd, int ywr, const int* __restrict__ nbrl,
    const float* __restrict__ fw3, const float* __restrict__ cb,
    const float* __restrict__ fb, const float* __restrict__ bag,
    const float* __restrict__ bab, const float* __restrict__ bbg,
    const float* __restrict__ bbb, int do_proj,
    const float* __restrict__ cwn, const float* __restrict__ fwn) {
    extern __shared__ char smem[];
    unsigned sbase = (unsigned)__cvta_generic_to_shared(smem);
    __nv_bfloat16* sBh = (__nv_bfloat16*)(smem + 1024);
    __nv_bfloat16* sBl = (__nv_bfloat16*)(smem + 53248);
    float* fs = (float*)(smem + 140288);
    float* ft = (float*)(smem + 140800);
    int* nb = (int*)(smem + 141568);
    float* xb = (float*)(smem + 142336);
    float* pb = (float*)(smem + 146688);
    float* y1s = (float*)(smem + 147968);
    float* y2s = (float*)(smem + 1024);    // reuse sBh after logits
    float* Cs = (float*)(smem + 53248);    // reuse sBl after logits
    unsigned mb0 = sbase + 16, mb1 = sbase + 24;

    const float* Xc = flip ? g_X1 : g_X0;
    float* Xn = flip ? g_X0 : g_X1;
    const float* Y1r = g_Y1[yrd];
    const float* Y2r = g_Y2[yrd];
    const float* S1r = g_S1[yrd];
    const float* S2r = g_S2[yrd];

    int tid = threadIdx.x;
    int lane = tid & 31, w = tid >> 5;
    int b = blockIdx.x >> 6;
    int n0 = (blockIdx.x & 63) << 4;
    int bn0 = b * 1024 + n0;

    if (tid == 0) {
        mbar_init(mb0, 1);
        mbar_init(mb1, 1);
        mbar_expect(mb0, 52224 + 34816);
        mbar_expect(mb1, 52224);
    }
    __syncthreads();

    const char* blob = (const char*)(g_BB + (size_t)blockIdx.x * 52224);
    if (tid == 0) {
        bulk_cp(sbase + 1024, blob, 52224, mb0);
    } else if (tid == 1) {
        bulk_cp(sbase + 105472, (const char*)&g_WA[l][0], 34816, mb0);
    } else if (tid == 2) {
        bulk_cp(sbase + 53248, blob + 52224, 52224, mb1);
    } else if (tid >= 128 && tid < 256) {
        fs[tid - 128] = __ldg(fw3 + tid - 128);
    } else if (tid >= 448) {
        int c = tid - 448;
        pb[c] = cb[c];
        pb[64 + c] = bag[c];
        pb[128 + c] = bab[c];
        pb[192 + c] = bbg[c];
        pb[256 + c] = bbb[c];
    }
    __syncthreads();   // fs/pb visible

    // ---- GEMM: 3 passes over (A image, W image) ----
    int wm = w & 3, wn = w >> 2;
    unsigned laneoff = ((lane & 15) * 136 + (lane >> 4) * 8) * 2;
    int bloff = (lane >> 2) * 68 + (lane & 3);
    float d[3][2][4];
#pragma unroll
    for (int mt = 0; mt < 3; mt++)
#pragma unroll
        for (int nt = 0; nt < 2; nt++)
#pragma unroll
            for (int fr = 0; fr < 4; fr++) d[mt][nt][fr] = 0.f;

#pragma unroll 1
    for (int p = 0; p < 3; p++) {
        if (p == 0) mbar_wait(mb0);
        if (p == 2) mbar_wait(mb1);
        unsigned abase = sbase + (p == 2 ? 53248u : 1024u) + laneoff +
                         (unsigned)(wm * 48 * 272);
        const unsigned* Wp =
            (const unsigned*)(smem + (p == 1 ? 122880 : 105472));
#pragma unroll
        for (int ks = 0; ks < 8; ks++) {
            int k0 = ks * 16;
            unsigned bfr[2][2];
#pragma unroll
            for (int nt = 0; nt < 2; nt++) {
                int idx = (wn * 16 + nt * 8) * 68 + (k0 >> 1) + bloff;
                bfr[nt][0] = Wp[idx];
                bfr[nt][1] = Wp[idx + 4];
            }
#pragma unroll
            for (int mt = 0; mt < 3; mt++) {
                unsigned afr[4];
                ldmx4(afr, abase + mt * (16 * 272) + k0 * 2);
                mma16816(d[mt][0], afr, bfr[0]);
                mma16816(d[mt][1], afr, bfr[1]);
            }
        }
    }

    // ---- filter logits (reads sBh+sBl before they are reused) ----
    if (tid < 192) {
        int row = tid;
        int a_ = row / 12, m = row - a_ * 12;
        int nbr = nbrl[(bn0 + a_) * 12 + m];
        nb[row] = nbr;
        const __nv_bfloat16* ph = sBh + row * 136;
        const __nv_bfloat16* pl = sBl + row * 136;
        float acc2 = 0.f;
#pragma unroll
        for (int k = 0; k < 128; k += 8) {
            uint4 uh = *(const uint4*)(ph + k);
            uint4 ul = *(const uint4*)(pl + k);
            float2 h0 = bf2(uh.x), h1 = bf2(uh.y), h2 = bf2(uh.z),
                   h3 = bf2(uh.w);
            float2 q0 = bf2(ul.x), q1 = bf2(ul.y), q2 = bf2(ul.z),
                   q3 = bf2(ul.w);
            acc2 += (h0.x + q0.x) * fs[k] + (h0.y + q0.y) * fs[k + 1] +
                    (h1.x + q1.x) * fs[k + 2] + (h1.y + q1.y) * fs[k + 3] +
                    (h2.x + q2.x) * fs[k + 4] + (h2.y + q2.y) * fs[k + 5] +
                    (h3.x + q3.x) * fs[k + 6] + (h3.y + q3.y) * fs[k + 7];
        }
        ft[row] = acc2 + S1r[bn0 + a_] + S2r[b * 1024 + nbr] + fb[0];
    }
    __syncthreads();

    // ---- stage y1/y2 into smem (coalesced) + softmax over m ----
    for (int i = tid; i < 3072; i += 512) {
        int row = i >> 4, q = i & 15;
        *(float4*)(y2s + row * 64 + q * 4) =
            *(const float4*)(Y2r + (b * 1024 + nb[row]) * 64 + q * 4);
    }
    if (tid < 256) {
        int a = tid >> 4, q = tid & 15;
        *(float4*)(y1s + a * 64 + q * 4) =
            *(const float4*)(Y1r + (bn0 + a) * 64 + q * 4);
    }
    if (w == 15 && lane < 16) {
        int base = lane * 12;
        float mx = -1e30f;
#pragma unroll
        for (int m = 0; m < 12; m++) mx = fmaxf(mx, ft[base + m]);
        float s = 0.f;
#pragma unroll
        for (int m = 0; m < 12; m++) s += expf(ft[base + m] - mx);
        float inv = 1.f / (12.f * s);
#pragma unroll
        for (int m = 0; m < 12; m++)
            ft[base + m] = expf(ft[base + m] - mx) * inv;
    }
    __syncthreads();

    // ---- epilogue: frag + y1 + y2 + cb -> BN -> relu -> Cs ----
#pragma unroll
    for (int mt = 0; mt < 3; mt++) {
        int r0 = wm * 48 + mt * 16 + (lane >> 2);
#pragma unroll
        for (int nt = 0; nt < 2; nt++) {
            int c0 = wn * 16 + nt * 8 + (lane & 3) * 2;
#pragma unroll
            for (int fr = 0; fr < 4; fr++) {
                int row = r0 + (fr >> 1) * 8;
                int c = c0 + (fr & 1);
                int a_ = row / 12;
                float v = d[mt][nt][fr] + y1s[a_ * 64 + c] +
                          y2s[row * 64 + c] + pb[c];
                v = fmaxf(pb[64 + c] * (v * BN_ALPHA) + pb[128 + c], 0.f);
                Cs[row * 65 + c] = v;
            }
        }
    }
    __syncthreads();

    // ---- weighted mean, BN, residual relu; stash xn ----
#pragma unroll
    for (int q = 0; q < 2; q++) {
        int idx = tid + 512 * q;
        int a_ = idx >> 6, c = idx & 63;
        float s = 0.f;
#pragma unroll
        for (int m = 0; m < 12; m++)
            s += ft[a_ * 12 + m] * Cs[(a_ * 12 + m) * 65 + c];
        s = pb[192 + c] * (s * BN_ALPHA) + pb[256 + c];
        int gi = (bn0 + a_) * 64 + c;
        float xv = fmaxf(Xc[gi] + s, 0.f);
        Xn[gi] = xv;
        xb[a_ * 68 + c] = xv;
    }
    __syncthreads();

    // ---- fused next-layer projection (write buffer ywr) ----
    if (do_proj && tid < 260) {
        int rg2 = (tid >= 130) ? 1 : 0;
        int c2 = tid - rg2 * 130;
        proj8(xb, bn0, rg2 * 8, c2, ywr, cwn, fwn);
    }
}

// ---------------------------------------------------------------------------
__global__ void __launch_bounds__(256) final_k(const int* __restrict__ tix,
                                               const float* __restrict__ dw,
                                               const float* __restrict__ db,
                                               float* __restrict__ out) {
    __shared__ float cs[64 * 68];
    __shared__ float wd[64 * 65];
    int b = blockIdx.x, tid = threadIdx.x;
    for (int t = tid; t < 4096; t += 256) {
        int k = t >> 6, f = t & 63;
        wd[k * 65 + f] = dw[t];
    }
    for (int t = tid; t < 1024; t += 256) {
        int j = t >> 4, q = t & 15;
        int ti = tix[b * 64 + j];
        float4 v = *(const float4*)(g_X1 + (b * 1024 + ti) * 64 + q * 4);
        v.x = fmaxf(v.x, 0.f);
        v.y = fmaxf(v.y, 0.f);
        v.z = fmaxf(v.z, 0.f);
        v.w = fmaxf(v.w, 0.f);
        *(float4*)(cs + j * 68 + q * 4) = v;
    }
    __syncthreads();
    for (int t = tid; t < 4096; t += 256) {
        int j = t >> 6, f = t & 63;
        float acc = db[f];
#pragma unroll 8
        for (int k = 0; k < 64; k++) acc += cs[j * 68 + k] * wd[k * 65 + f];
        out[b * 4096 + t] = fmaxf(acc, 0.f);
    }
}

// ---------------------------------------------------------------------------
extern "C" void kernel_launch(void* const* d_in, const int* in_sizes, int n_in,
                              void* d_out, int out_size) {
    const int* atom_types = (const int*)d_in[0];
    const float* bond = (const float*)d_in[1];
    const int* nbrl = (const int*)d_in[2];
    const int* tix = (const int*)d_in[3];
    const float* emb = (const float*)d_in[4];
    const float* core_w = (const float*)d_in[5];
    const float* core_b = (const float*)d_in[6];
    const float* filt_w = (const float*)d_in[7];
    const float* filt_b = (const float*)d_in[8];
    const float* bna_g = (const float*)d_in[9];
    const float* bna_b = (const float*)d_in[10];
    const float* bnb_g = (const float*)d_in[11];
    const float* bnb_b = (const float*)d_in[12];
    const float* dw = (const float*)d_in[13];
    const float* db = (const float*)d_in[14];
    float* out = (float*)d_out;

    cudaFuncSetAttribute(conv_k, cudaFuncAttributeMaxDynamicSharedMemorySize,
                         CONV_SMEM);

    prep_w_k<<<3, 256>>>(core_w);
    prep_bond_k<<<1024, 384>>>(bond);
    embed_proj_k<<<1024, 256>>>(atom_types, emb, core_w, filt_w);
    for (int l = 0; l < 3; l++) {
        int flip = l & 1;
        int yrd = l & 1;
        int ywr = (l + 1) & 1;
        int do_proj = (l < 2) ? 1 : 0;
        const float* cwn = core_w + (l + 1 < 3 ? (l + 1) : l) * 256 * 64;
        const float* fwn = filt_w + (l + 1 < 3 ? (l + 1) : l) * 256;
        conv_k<<<1024, 512, CONV_SMEM>>>(
            l, flip, yrd, ywr, nbrl, filt_w + l * 256 + 128, core_b + l * 64,
            filt_b + l, bna_g + l * 64, bna_b + l * 64, bnb_g + l * 64,
            bnb_b + l * 64, do_proj, cwn, fwn);
    }
    final_k<<<16, 256>>>(tix, dw, db, out);
}

// round 10
// speedup vs baseline: 1.5791x; 1.5791x over previous
#include <cuda_runtime.h>
#include <cuda_bf16.h>

// ---------------------------------------------------------------------------
// CGCNN: B=16, N=1024, M=12, F=64, BF=128, N_CONV=3, VOCAB=100
// total@W = x@W1 + gather(x@W2) + bond@W3 ; proj fused into conv/embed.
// Bond GEMM via mma.sync m16n8k16 bf16 hi/lo split: bh*Wh + bh*Wl + bl*Wh.
// conv: 8 atoms/block (96 rows), 256 threads, 2 blocks/SM.
// ---------------------------------------------------------------------------

#define BN_ALPHA 0.99950037f   // 1/sqrt(1+1e-3)

__device__ float g_X0[16 * 1024 * 64];
__device__ float g_X1[16 * 1024 * 64];
__device__ float g_Y1[2][16 * 1024 * 64];
__device__ float g_Y2[2][16 * 1024 * 64];
__device__ float g_S1[2][16 * 1024];
__device__ float g_S2[2][16 * 1024];
__device__ __nv_bfloat16 g_WA[3][2 * 64 * 136];          // WT [hi|lo], n-major
__device__ __nv_bfloat16 g_BB[1024ull * 2 * 192 * 136];  // bond [hi|lo]/tile

// ---- mbarrier / bulk helpers ----------------------------------------------
__device__ __forceinline__ void mbar_init(unsigned m, unsigned c) {
    asm volatile("mbarrier.init.shared.b64 [%0], %1;" ::"r"(m), "r"(c)
                 : "memory");
}
__device__ __forceinline__ void mbar_expect(unsigned m, unsigned b) {
    asm volatile("mbarrier.arrive.expect_tx.shared.b64 _, [%0], %1;" ::"r"(m),
                 "r"(b)
                 : "memory");
}
__device__ __forceinline__ void mbar_wait(unsigned m) {
    asm volatile(
        "{\n\t.reg .pred P;\n\tW%=:\n\t"
        "mbarrier.try_wait.parity.acquire.cta.shared::cta.b64 P, [%0], 0;\n\t"
        "@!P bra W%=;\n\t}" ::"r"(m)
        : "memory");
}
__device__ __forceinline__ void bulk_cp(unsigned d, const void* s, unsigned b,
                                        unsigned m) {
    asm volatile(
        "cp.async.bulk.shared::cta.global.mbarrier::complete_tx::bytes "
        "[%0], [%1], %2, [%3];" ::"r"(d),
        "l"(s), "r"(b), "r"(m)
        : "memory");
}

// ---- tensor-core helpers (sm_80+ PTX) -------------------------------------
__device__ __forceinline__ void mma16816(float* d, const unsigned* a,
                                         const unsigned* b) {
    asm volatile(
        "mma.sync.aligned.m16n8k16.row.col.f32.bf16.bf16.f32 "
        "{%0,%1,%2,%3}, {%4,%5,%6,%7}, {%8,%9}, {%0,%1,%2,%3};"
        : "+f"(d[0]), "+f"(d[1]), "+f"(d[2]), "+f"(d[3])
        : "r"(a[0]), "r"(a[1]), "r"(a[2]), "r"(a[3]), "r"(b[0]), "r"(b[1]));
}
__device__ __forceinline__ void ldmx4(unsigned* a, unsigned addr) {
    asm volatile(
        "ldmatrix.sync.aligned.m8n8.x4.shared.b16 {%0,%1,%2,%3}, [%4];"
        : "=r"(a[0]), "=r"(a[1]), "=r"(a[2]), "=r"(a[3])
        : "r"(addr));
}
__device__ __forceinline__ float2 bf2(unsigned u) {
    __nv_bfloat162 h = reinterpret_cast<__nv_bfloat162&>(u);
    return __bfloat1622float2(h);
}

// ---------------------------------------------------------------------------
// prep_w_k: WT[n][k] bf16 hi/lo, rows padded to 136. grid 3 x 256.
// ---------------------------------------------------------------------------
__global__ void __launch_bounds__(256) prep_w_k(const float* __restrict__ cw) {
    int l = blockIdx.x;
    const float* W = cw + l * 256 * 64 + 128 * 64;   // [k][n]
    for (int t = threadIdx.x; t < 8192; t += 256) {
        int n = t >> 7, k = t & 127;
        float wv = W[k * 64 + n];
        __nv_bfloat16 h = __float2bfloat16(wv);
        g_WA[l][n * 136 + k] = h;
        g_WA[l][8704 + n * 136 + k] =
            __float2bfloat16(wv - __bfloat162float(h));
    }
}

// ---------------------------------------------------------------------------
// prep_bond_k: per 16-atom tile (192 rows) emit [hi 192x136 | lo 192x136]
// bf16 row-major. COALESCED: thread unit = 16B chunk (8 cols) of one row.
// grid 1024 x 256.
// ---------------------------------------------------------------------------
__global__ void __launch_bounds__(256) prep_bond_k(
    const float* __restrict__ bond) {
    size_t tile = blockIdx.x;
    const float* src = bond + tile * 192 * 128;
    __nv_bfloat16* dh = g_BB + tile * 52224;
    __nv_bfloat16* dl = dh + 26112;
    for (int i = threadIdx.x; i < 192 * 16; i += 256) {
        int row = i >> 4, q = i & 15;
        const float* s = src + row * 128 + q * 8;
        float4 v0 = *(const float4*)s;
        float4 v1 = *(const float4*)(s + 4);
        float v[8] = {v0.x, v0.y, v0.z, v0.w, v1.x, v1.y, v1.z, v1.w};
        unsigned hu[4], lu[4];
#pragma unroll
        for (int p = 0; p < 4; p++) {
            __nv_bfloat16 h0 = __float2bfloat16(v[2 * p]);
            __nv_bfloat16 h1 = __float2bfloat16(v[2 * p + 1]);
            __nv_bfloat162 hh, ll;
            hh.x = h0;
            hh.y = h1;
            ll.x = __float2bfloat16(v[2 * p] - __bfloat162float(h0));
            ll.y = __float2bfloat16(v[2 * p + 1] - __bfloat162float(h1));
            hu[p] = reinterpret_cast<unsigned&>(hh);
            lu[p] = reinterpret_cast<unsigned&>(ll);
        }
        *(uint4*)(dh + row * 136 + q * 8) = make_uint4(hu[0], hu[1], hu[2], hu[3]);
        *(uint4*)(dl + row * 136 + q * 8) = make_uint4(lu[0], lu[1], lu[2], lu[3]);
    }
}

// ---------------------------------------------------------------------------
// proj8 + embed (exact fp32)
// ---------------------------------------------------------------------------
__device__ __forceinline__ void proj8(const float* __restrict__ xs, int bn0,
                                      int r0, int c2, int yb,
                                      const float* __restrict__ cwn,
                                      const float* __restrict__ fwn) {
    const float* wp;
    int st;
    if (c2 < 64) {
        wp = cwn + c2;
        st = 64;
    } else if (c2 < 128) {
        wp = cwn + 64 * 64 + (c2 - 64);
        st = 64;
    } else {
        wp = fwn + (c2 - 128) * 64;
        st = 1;
    }
    float acc[8] = {0.f, 0.f, 0.f, 0.f, 0.f, 0.f, 0.f, 0.f};
#pragma unroll 8
    for (int k = 0; k < 64; k++) {
        float wv = __ldg(wp + k * st);
#pragma unroll
        for (int rr = 0; rr < 8; rr++) acc[rr] += xs[(r0 + rr) * 68 + k] * wv;
    }
    if (c2 < 64) {
#pragma unroll
        for (int rr = 0; rr < 8; rr++)
            g_Y1[yb][(bn0 + r0 + rr) * 64 + c2] = acc[rr];
    } else if (c2 < 128) {
#pragma unroll
        for (int rr = 0; rr < 8; rr++)
            g_Y2[yb][(bn0 + r0 + rr) * 64 + (c2 - 64)] = acc[rr];
    } else if (c2 == 128) {
#pragma unroll
        for (int rr = 0; rr < 8; rr++) g_S1[yb][bn0 + r0 + rr] = acc[rr];
    } else {
#pragma unroll
        for (int rr = 0; rr < 8; rr++) g_S2[yb][bn0 + r0 + rr] = acc[rr];
    }
}

__global__ void __launch_bounds__(256) embed_proj_k(
    const int* __restrict__ types, const float* __restrict__ emb,
    const float* __restrict__ cwn, const float* __restrict__ fwn) {
    __shared__ float xs[16 * 68];
    int tid = threadIdx.x;
    int bn0 = blockIdx.x * 16;
    {
        int r = tid >> 4, q = tid & 15;
        int t = types[bn0 + r];
        float4 v = *(const float4*)(emb + t * 64 + q * 4);
        *(float4*)(xs + r * 68 + q * 4) = v;
        *(float4*)(g_X0 + (bn0 + r) * 64 + q * 4) = v;
    }
    __syncthreads();
    if (tid < 130) {
        proj8(xs, bn0, 0, tid, 0, cwn, fwn);
        proj8(xs, bn0, 8, tid, 0, cwn, fwn);
    }
}

// ---------------------------------------------------------------------------
// conv_k: one block = 8 atoms (96 rows), 256 threads, 2 blocks/SM.
// 8 warps = 2 row-groups (48) x 4 col-groups (16). 3 mma passes.
// smem (bytes): 16,24 mbars | 1024 sBh(26112) | 27136 sBl(26112) |
// 53248 sWh(17408) | 70656 sWl(17408) | 88064 fs(512) | 88576 ft(384) |
// 88960 nb(384) | 89344 xb(2176) | 91520 pb(1280) | 92800 y1s(2048) -> 94848
// reuse after logits: y2s = sBh, Cs = sBl.
// ---------------------------------------------------------------------------
#define CONV_SMEM 94848

__global__ void __launch_bounds__(256, 2) conv_k(
    int l, int flip, int yrd, int ywr, const int* __restrict__ nbrl,
    const float* __restrict__ fw3, const float* __restrict__ cb,
    const float* __restrict__ fb, const float* __restrict__ bag,
    const float* __restrict__ bab, const float* __restrict__ bbg,
    const float* __restrict__ bbb, int do_proj,
    const float* __restrict__ cwn, const float* __restrict__ fwn) {
    extern __shared__ char smem[];
    unsigned sbase = (unsigned)__cvta_generic_to_shared(smem);
    __nv_bfloat16* sBh = (__nv_bfloat16*)(smem + 1024);
    __nv_bfloat16* sBl = (__nv_bfloat16*)(smem + 27136);
    float* fs = (float*)(smem + 88064);
    float* ft = (float*)(smem + 88576);
    int* nb = (int*)(smem + 88960);
    float* xb = (float*)(smem + 89344);
    float* pb = (float*)(smem + 91520);
    float* y1s = (float*)(smem + 92800);
    float* y2s = (float*)(smem + 1024);    // reuse sBh after logits
    float* Cs = (float*)(smem + 27136);    // reuse sBl after logits
    unsigned mb0 = sbase + 16, mb1 = sbase + 24;

    const float* Xc = flip ? g_X1 : g_X0;
    float* Xn = flip ? g_X0 : g_X1;
    const float* Y1r = g_Y1[yrd];
    const float* Y2r = g_Y2[yrd];
    const float* S1r = g_S1[yrd];
    const float* S2r = g_S2[yrd];

    int tid = threadIdx.x;
    int lane = tid & 31, w = tid >> 5;
    int bn0 = blockIdx.x * 8;          // 8 atoms per block
    int b = bn0 >> 10;

    if (tid == 0) {
        mbar_init(mb0, 1);
        mbar_init(mb1, 1);
        mbar_expect(mb0, 26112 + 34816);
        mbar_expect(mb1, 26112);
    }
    __syncthreads();

    // half-tile blob: rows contiguous inside each image
    size_t tile = blockIdx.x >> 1;
    unsigned half = blockIdx.x & 1;
    const char* bh = (const char*)(g_BB + tile * 52224 + half * 96 * 136);
    const char* bl = bh + 26112 * 2;   // +26112 elements = 52224 bytes? no:
    // lo image starts +26112 elements from tile base; recompute directly:
    const char* blo =
        (const char*)(g_BB + tile * 52224 + 26112 + half * 96 * 136);

    if (tid == 0) {
        bulk_cp(sbase + 1024, bh, 26112, mb0);
    } else if (tid == 1) {
        bulk_cp(sbase + 53248, (const char*)&g_WA[l][0], 34816, mb0);
    } else if (tid == 2) {
        bulk_cp(sbase + 27136, blo, 26112, mb1);
    } else if (tid >= 64 && tid < 192) {
        fs[tid - 64] = __ldg(fw3 + tid - 64);
    } else if (tid >= 192) {
        int c = tid - 192;
        pb[c] = cb[c];
        pb[64 + c] = bag[c];
        pb[128 + c] = bab[c];
        pb[192 + c] = bbg[c];
        pb[256 + c] = bbb[c];
    }
    __syncthreads();   // fs/pb visible

    // ---- GEMM: 3 passes (bh*Wh, bh*Wl, bl*Wh) ----
    int wm = w & 1, wn = w >> 1;
    unsigned laneoff = ((lane & 15) * 136 + (lane >> 4) * 8) * 2;
    int bloff = (lane >> 2) * 68 + (lane & 3);
    float d[3][2][4];
#pragma unroll
    for (int mt = 0; mt < 3; mt++)
#pragma unroll
        for (int nt = 0; nt < 2; nt++)
#pragma unroll
            for (int fr = 0; fr < 4; fr++) d[mt][nt][fr] = 0.f;

#pragma unroll 1
    for (int p = 0; p < 3; p++) {
        if (p == 0) mbar_wait(mb0);
        if (p == 2) mbar_wait(mb1);
        unsigned abase = sbase + (p == 2 ? 27136u : 1024u) + laneoff +
                         (unsigned)(wm * 48 * 272);
        const unsigned* Wp =
            (const unsigned*)(smem + (p == 1 ? 70656 : 53248));
#pragma unroll
        for (int ks = 0; ks < 8; ks++) {
            int k0 = ks * 16;
            unsigned bfr[2][2];
#pragma unroll
            for (int nt = 0; nt < 2; nt++) {
                int idx = (wn * 16 + nt * 8) * 68 + (k0 >> 1) + bloff;
                bfr[nt][0] = Wp[idx];
                bfr[nt][1] = Wp[idx + 4];
            }
#pragma unroll
            for (int mt = 0; mt < 3; mt++) {
                unsigned afr[4];
                ldmx4(afr, abase + mt * (16 * 272) + k0 * 2);
                mma16816(d[mt][0], afr, bfr[0]);
                mma16816(d[mt][1], afr, bfr[1]);
            }
        }
    }

    // ---- filter logits (reads sBh+sBl before reuse) ----
    if (tid < 96) {
        int row = tid;
        int a_ = row / 12, m = row - a_ * 12;
        int nbr = nbrl[(bn0 + a_) * 12 + m];
        nb[row] = nbr;
        const __nv_bfloat16* ph = sBh + row * 136;
        const __nv_bfloat16* pl = sBl + row * 136;
        float acc2 = 0.f;
#pragma unroll
        for (int k = 0; k < 128; k += 8) {
            uint4 uh = *(const uint4*)(ph + k);
            uint4 ul = *(const uint4*)(pl + k);
            float2 h0 = bf2(uh.x), h1 = bf2(uh.y), h2 = bf2(uh.z),
                   h3 = bf2(uh.w);
            float2 q0 = bf2(ul.x), q1 = bf2(ul.y), q2 = bf2(ul.z),
                   q3 = bf2(ul.w);
            acc2 += (h0.x + q0.x) * fs[k] + (h0.y + q0.y) * fs[k + 1] +
                    (h1.x + q1.x) * fs[k + 2] + (h1.y + q1.y) * fs[k + 3] +
                    (h2.x + q2.x) * fs[k + 4] + (h2.y + q2.y) * fs[k + 5] +
                    (h3.x + q3.x) * fs[k + 6] + (h3.y + q3.y) * fs[k + 7];
        }
        ft[row] = acc2 + S1r[bn0 + a_] + S2r[b * 1024 + nbr] + fb[0];
    }
    __syncthreads();

    // ---- stage y1/y2 (coalesced) + softmax over m ----
    for (int i = tid; i < 1536; i += 256) {
        int row = i >> 4, q = i & 15;
        *(float4*)(y2s + row * 64 + q * 4) =
            *(const float4*)(Y2r + (b * 1024 + nb[row]) * 64 + q * 4);
    }
    if (tid < 128) {
        int a = tid >> 4, q = tid & 15;
        *(float4*)(y1s + a * 64 + q * 4) =
            *(const float4*)(Y1r + (bn0 + a) * 64 + q * 4);
    }
    if (w == 7 && lane < 8) {
        int base = lane * 12;
        float mx = -1e30f;
#pragma unroll
        for (int m = 0; m < 12; m++) mx = fmaxf(mx, ft[base + m]);
        float s = 0.f;
#pragma unroll
        for (int m = 0; m < 12; m++) s += expf(ft[base + m] - mx);
        float inv = 1.f / (12.f * s);
#pragma unroll
        for (int m = 0; m < 12; m++)
            ft[base + m] = expf(ft[base + m] - mx) * inv;
    }
    __syncthreads();

    // ---- epilogue: frag + y1 + y2 + cb -> BN -> relu -> Cs ----
#pragma unroll
    for (int mt = 0; mt < 3; mt++) {
        int r0 = wm * 48 + mt * 16 + (lane >> 2);
#pragma unroll
        for (int nt = 0; nt < 2; nt++) {
            int c0 = wn * 16 + nt * 8 + (lane & 3) * 2;
#pragma unroll
            for (int fr = 0; fr < 4; fr++) {
                int row = r0 + (fr >> 1) * 8;
                int c = c0 + (fr & 1);
                int a_ = row / 12;
                float v = d[mt][nt][fr] + y1s[a_ * 64 + c] +
                          y2s[row * 64 + c] + pb[c];
                v = fmaxf(pb[64 + c] * (v * BN_ALPHA) + pb[128 + c], 0.f);
                Cs[row * 65 + c] = v;
            }
        }
    }
    __syncthreads();

    // ---- weighted mean, BN, residual relu; stash xn ----
#pragma unroll
    for (int q = 0; q < 2; q++) {
        int idx = tid + 256 * q;   // < 512 = 8*64
        int a_ = idx >> 6, c = idx & 63;
        float s = 0.f;
#pragma unroll
        for (int m = 0; m < 12; m++)
            s += ft[a_ * 12 + m] * Cs[(a_ * 12 + m) * 65 + c];
        s = pb[192 + c] * (s * BN_ALPHA) + pb[256 + c];
        int gi = (bn0 + a_) * 64 + c;
        float xv = fmaxf(Xc[gi] + s, 0.f);
        Xn[gi] = xv;
        xb[a_ * 68 + c] = xv;
    }
    __syncthreads();

    // ---- fused next-layer projection (8 atoms, write buffer ywr) ----
    if (do_proj && tid < 130) {
        proj8(xb, bn0, 0, tid, ywr, cwn, fwn);
    }
}

// ---------------------------------------------------------------------------
__global__ void __launch_bounds__(256) final_k(const int* __restrict__ tix,
                                               const float* __restrict__ dw,
                                               const float* __restrict__ db,
                                               float* __restrict__ out) {
    __shared__ float cs[64 * 68];
    __shared__ float wd[64 * 65];
    int b = blockIdx.x, tid = threadIdx.x;
    for (int t = tid; t < 4096; t += 256) {
        int k = t >> 6, f = t & 63;
        wd[k * 65 + f] = dw[t];
    }
    for (int t = tid; t < 1024; t += 256) {
        int j = t >> 4, q = t & 15;
        int ti = tix[b * 64 + j];
        float4 v = *(const float4*)(g_X1 + (b * 1024 + ti) * 64 + q * 4);
        v.x = fmaxf(v.x, 0.f);
        v.y = fmaxf(v.y, 0.f);
        v.z = fmaxf(v.z, 0.f);
        v.w = fmaxf(v.w, 0.f);
        *(float4*)(cs + j * 68 + q * 4) = v;
    }
    __syncthreads();
    for (int t = tid; t < 4096; t += 256) {
        int j = t >> 6, f = t & 63;
        float acc = db[f];
#pragma unroll 8
        for (int k = 0; k < 64; k++) acc += cs[j * 68 + k] * wd[k * 65 + f];
        out[b * 4096 + t] = fmaxf(acc, 0.f);
    }
}

// ---------------------------------------------------------------------------
extern "C" void kernel_launch(void* const* d_in, const int* in_sizes, int n_in,
                              void* d_out, int out_size) {
    const int* atom_types = (const int*)d_in[0];
    const float* bond = (const float*)d_in[1];
    const int* nbrl = (const int*)d_in[2];
    const int* tix = (const int*)d_in[3];
    const float* emb = (const float*)d_in[4];
    const float* core_w = (const float*)d_in[5];
    const float* core_b = (const float*)d_in[6];
    const float* filt_w = (const float*)d_in[7];
    const float* filt_b = (const float*)d_in[8];
    const float* bna_g = (const float*)d_in[9];
    const float* bna_b = (const float*)d_in[10];
    const float* bnb_g = (const float*)d_in[11];
    const float* bnb_b = (const float*)d_in[12];
    const float* dw = (const float*)d_in[13];
    const float* db = (const float*)d_in[14];
    float* out = (float*)d_out;

    cudaFuncSetAttribute(conv_k, cudaFuncAttributeMaxDynamicSharedMemorySize,
                         CONV_SMEM);

    prep_w_k<<<3, 256>>>(core_w);
    prep_bond_k<<<1024, 256>>>(bond);
    embed_proj_k<<<1024, 256>>>(atom_types, emb, core_w, filt_w);
    for (int l = 0; l < 3; l++) {
        int flip = l & 1;
        int yrd = l & 1;
        int ywr = (l + 1) & 1;
        int do_proj = (l < 2) ? 1 : 0;
        const float* cwn = core_w + (l + 1 < 3 ? (l + 1) : l) * 256 * 64;
        const float* fwn = filt_w + (l + 1 < 3 ? (l + 1) : l) * 256;
        conv_k<<<2048, 256, CONV_SMEM>>>(
            l, flip, yrd, ywr, nbrl, filt_w + l * 256 + 128, core_b + l * 64,
            filt_b + l, bna_g + l * 64, bna_b + l * 64, bnb_g + l * 64,
            bnb_b + l * 64, do_proj, cwn, fwn);
    }
    final_k<<<16, 256>>>(tix, dw, db, out);
}

// round 11
// speedup vs baseline: 1.6774x; 1.0622x over previous
#include <cuda_runtime.h>
#include <cuda_bf16.h>

// ---------------------------------------------------------------------------
// CGCNN: B=16, N=1024, M=12, F=64, BF=128, N_CONV=3, VOCAB=100
// total@W = x@W1 + gather(x@W2) + bond@W3 ; proj fused into conv/embed.
// Bond GEMM via mma.sync m16n8k16 bf16 hi/lo split: bh*(Wh+Wl) + bl*Wh.
// conv: 8 atoms/block (96 rows), 256 threads, 2 blocks/SM.
// R11: fused hi passes (A LDSM 3->2 loads) + vectorized proj8.
// ---------------------------------------------------------------------------

#define BN_ALPHA 0.99950037f   // 1/sqrt(1+1e-3)

__device__ float g_X0[16 * 1024 * 64];
__device__ float g_X1[16 * 1024 * 64];
__device__ float g_Y1[2][16 * 1024 * 64];
__device__ float g_Y2[2][16 * 1024 * 64];
__device__ float g_S1[2][16 * 1024];
__device__ float g_S2[2][16 * 1024];
__device__ __nv_bfloat16 g_WA[3][2 * 64 * 136];          // WT [hi|lo], n-major
__device__ __nv_bfloat16 g_BB[1024ull * 2 * 192 * 136];  // bond [hi|lo]/tile

// ---- mbarrier / bulk helpers ----------------------------------------------
__device__ __forceinline__ void mbar_init(unsigned m, unsigned c) {
    asm volatile("mbarrier.init.shared.b64 [%0], %1;" ::"r"(m), "r"(c)
                 : "memory");
}
__device__ __forceinline__ void mbar_expect(unsigned m, unsigned b) {
    asm volatile("mbarrier.arrive.expect_tx.shared.b64 _, [%0], %1;" ::"r"(m),
                 "r"(b)
                 : "memory");
}
__device__ __forceinline__ void mbar_wait(unsigned m) {
    asm volatile(
        "{\n\t.reg .pred P;\n\tW%=:\n\t"
        "mbarrier.try_wait.parity.acquire.cta.shared::cta.b64 P, [%0], 0;\n\t"
        "@!P bra W%=;\n\t}" ::"r"(m)
        : "memory");
}
__device__ __forceinline__ void bulk_cp(unsigned d, const void* s, unsigned b,
                                        unsigned m) {
    asm volatile(
        "cp.async.bulk.shared::cta.global.mbarrier::complete_tx::bytes "
        "[%0], [%1], %2, [%3];" ::"r"(d),
        "l"(s), "r"(b), "r"(m)
        : "memory");
}

// ---- tensor-core helpers (sm_80+ PTX) -------------------------------------
__device__ __forceinline__ void mma16816(float* d, const unsigned* a,
                                         const unsigned* b) {
    asm volatile(
        "mma.sync.aligned.m16n8k16.row.col.f32.bf16.bf16.f32 "
        "{%0,%1,%2,%3}, {%4,%5,%6,%7}, {%8,%9}, {%0,%1,%2,%3};"
        : "+f"(d[0]), "+f"(d[1]), "+f"(d[2]), "+f"(d[3])
        : "r"(a[0]), "r"(a[1]), "r"(a[2]), "r"(a[3]), "r"(b[0]), "r"(b[1]));
}
__device__ __forceinline__ void ldmx4(unsigned* a, unsigned addr) {
    asm volatile(
        "ldmatrix.sync.aligned.m8n8.x4.shared.b16 {%0,%1,%2,%3}, [%4];"
        : "=r"(a[0]), "=r"(a[1]), "=r"(a[2]), "=r"(a[3])
        : "r"(addr));
}
__device__ __forceinline__ float2 bf2(unsigned u) {
    __nv_bfloat162 h = reinterpret_cast<__nv_bfloat162&>(u);
    return __bfloat1622float2(h);
}

// ---------------------------------------------------------------------------
// prep_w_k: WT[n][k] bf16 hi/lo, rows padded to 136. grid 3 x 256.
// ---------------------------------------------------------------------------
__global__ void __launch_bounds__(256) prep_w_k(const float* __restrict__ cw) {
    int l = blockIdx.x;
    const float* W = cw + l * 256 * 64 + 128 * 64;   // [k][n]
    for (int t = threadIdx.x; t < 8192; t += 256) {
        int n = t >> 7, k = t & 127;
        float wv = W[k * 64 + n];
        __nv_bfloat16 h = __float2bfloat16(wv);
        g_WA[l][n * 136 + k] = h;
        g_WA[l][8704 + n * 136 + k] =
            __float2bfloat16(wv - __bfloat162float(h));
    }
}

// ---------------------------------------------------------------------------
// prep_bond_k: per 16-atom tile (192 rows) emit [hi 192x136 | lo 192x136]
// bf16 row-major, coalesced 16B-chunk mapping. grid 1024 x 256.
// ---------------------------------------------------------------------------
__global__ void __launch_bounds__(256) prep_bond_k(
    const float* __restrict__ bond) {
    size_t tile = blockIdx.x;
    const float* src = bond + tile * 192 * 128;
    __nv_bfloat16* dh = g_BB + tile * 52224;
    __nv_bfloat16* dl = dh + 26112;
    for (int i = threadIdx.x; i < 192 * 16; i += 256) {
        int row = i >> 4, q = i & 15;
        const float* s = src + row * 128 + q * 8;
        float4 v0 = *(const float4*)s;
        float4 v1 = *(const float4*)(s + 4);
        float v[8] = {v0.x, v0.y, v0.z, v0.w, v1.x, v1.y, v1.z, v1.w};
        unsigned hu[4], lu[4];
#pragma unroll
        for (int p = 0; p < 4; p++) {
            __nv_bfloat16 h0 = __float2bfloat16(v[2 * p]);
            __nv_bfloat16 h1 = __float2bfloat16(v[2 * p + 1]);
            __nv_bfloat162 hh, ll;
            hh.x = h0;
            hh.y = h1;
            ll.x = __float2bfloat16(v[2 * p] - __bfloat162float(h0));
            ll.y = __float2bfloat16(v[2 * p + 1] - __bfloat162float(h1));
            hu[p] = reinterpret_cast<unsigned&>(hh);
            lu[p] = reinterpret_cast<unsigned&>(ll);
        }
        *(uint4*)(dh + row * 136 + q * 8) =
            make_uint4(hu[0], hu[1], hu[2], hu[3]);
        *(uint4*)(dl + row * 136 + q * 8) =
            make_uint4(lu[0], lu[1], lu[2], lu[3]);
    }
}

// ---------------------------------------------------------------------------
// proj8 (VECTORIZED): 8 rows of x (smem, stride 68) -> Y1/Y2/S1/S2 buffer yb
// ---------------------------------------------------------------------------
__device__ __forceinline__ void proj8(const float* __restrict__ xs, int bn0,
                                      int r0, int c2, int yb,
                                      const float* __restrict__ cwn,
                                      const float* __restrict__ fwn) {
    const float* wp;
    int st;
    if (c2 < 64) {
        wp = cwn + c2;
        st = 64;
    } else if (c2 < 128) {
        wp = cwn + 64 * 64 + (c2 - 64);
        st = 64;
    } else {
        wp = fwn + (c2 - 128) * 64;
        st = 1;
    }
    float acc[8] = {0.f, 0.f, 0.f, 0.f, 0.f, 0.f, 0.f, 0.f};
#pragma unroll 2
    for (int k = 0; k < 64; k += 4) {
        float4 xv[8];
#pragma unroll
        for (int rr = 0; rr < 8; rr++)
            xv[rr] = *(const float4*)(xs + (r0 + rr) * 68 + k);
#pragma unroll
        for (int j = 0; j < 4; j++) {
            float wv = __ldg(wp + (k + j) * st);
#pragma unroll
            for (int rr = 0; rr < 8; rr++)
                acc[rr] += ((const float*)&xv[rr])[j] * wv;
        }
    }
    if (c2 < 64) {
#pragma unroll
        for (int rr = 0; rr < 8; rr++)
            g_Y1[yb][(bn0 + r0 + rr) * 64 + c2] = acc[rr];
    } else if (c2 < 128) {
#pragma unroll
        for (int rr = 0; rr < 8; rr++)
            g_Y2[yb][(bn0 + r0 + rr) * 64 + (c2 - 64)] = acc[rr];
    } else if (c2 == 128) {
#pragma unroll
        for (int rr = 0; rr < 8; rr++) g_S1[yb][bn0 + r0 + rr] = acc[rr];
    } else {
#pragma unroll
        for (int rr = 0; rr < 8; rr++) g_S2[yb][bn0 + r0 + rr] = acc[rr];
    }
}

__global__ void __launch_bounds__(256) embed_proj_k(
    const int* __restrict__ types, const float* __restrict__ emb,
    const float* __restrict__ cwn, const float* __restrict__ fwn) {
    __shared__ float xs[16 * 68];
    int tid = threadIdx.x;
    int bn0 = blockIdx.x * 16;
    {
        int r = tid >> 4, q = tid & 15;
        int t = types[bn0 + r];
        float4 v = *(const float4*)(emb + t * 64 + q * 4);
        *(float4*)(xs + r * 68 + q * 4) = v;
        *(float4*)(g_X0 + (bn0 + r) * 64 + q * 4) = v;
    }
    __syncthreads();
    if (tid < 130) {
        proj8(xs, bn0, 0, tid, 0, cwn, fwn);
        proj8(xs, bn0, 8, tid, 0, cwn, fwn);
    }
}

// ---------------------------------------------------------------------------
// conv_k: one block = 8 atoms (96 rows), 256 threads, 2 blocks/SM.
// 8 warps = 2 row-groups (48) x 4 col-groups (16).
// GEMM: fused pass0 (bh vs Wh AND Wl, same A frags) + pass1 (bl vs Wh).
// smem (bytes): 16,24 mbars | 1024 sBh(26112) | 27136 sBl(26112) |
// 53248 sWh(17408) | 70656 sWl(17408) | 88064 fs(512) | 88576 ft(384) |
// 88960 nb(384) | 89344 xb(2176) | 91520 pb(1280) | 92800 y1s(2048) -> 94848
// reuse after logits: y2s = sBh, Cs = sBl.
// ---------------------------------------------------------------------------
#define CONV_SMEM 94848

__global__ void __launch_bounds__(256, 2) conv_k(
    int l, int flip, int yrd, int ywr, const int* __restrict__ nbrl,
    const float* __restrict__ fw3, const float* __restrict__ cb,
    const float* __restrict__ fb, const float* __restrict__ bag,
    const float* __restrict__ bab, const float* __restrict__ bbg,
    const float* __restrict__ bbb, int do_proj,
    const float* __restrict__ cwn, const float* __restrict__ fwn) {
    extern __shared__ char smem[];
    unsigned sbase = (unsigned)__cvta_generic_to_shared(smem);
    __nv_bfloat16* sBh = (__nv_bfloat16*)(smem + 1024);
    __nv_bfloat16* sBl = (__nv_bfloat16*)(smem + 27136);
    float* fs = (float*)(smem + 88064);
    float* ft = (float*)(smem + 88576);
    int* nb = (int*)(smem + 88960);
    float* xb = (float*)(smem + 89344);
    float* pb = (float*)(smem + 91520);
    float* y1s = (float*)(smem + 92800);
    float* y2s = (float*)(smem + 1024);    // reuse sBh after logits
    float* Cs = (float*)(smem + 27136);    // reuse sBl after logits
    unsigned mb0 = sbase + 16, mb1 = sbase + 24;

    const float* Xc = flip ? g_X1 : g_X0;
    float* Xn = flip ? g_X0 : g_X1;
    const float* Y1r = g_Y1[yrd];
    const float* Y2r = g_Y2[yrd];
    const float* S1r = g_S1[yrd];
    const float* S2r = g_S2[yrd];

    int tid = threadIdx.x;
    int lane = tid & 31, w = tid >> 5;
    int bn0 = blockIdx.x * 8;          // 8 atoms per block
    int b = bn0 >> 10;

    if (tid == 0) {
        mbar_init(mb0, 1);
        mbar_init(mb1, 1);
        mbar_expect(mb0, 26112 + 34816);
        mbar_expect(mb1, 26112);
    }
    __syncthreads();

    size_t tile = blockIdx.x >> 1;
    unsigned half = blockIdx.x & 1;
    const char* bh = (const char*)(g_BB + tile * 52224 + half * 96 * 136);
    const char* blo =
        (const char*)(g_BB + tile * 52224 + 26112 + half * 96 * 136);

    if (tid == 0) {
        bulk_cp(sbase + 1024, bh, 26112, mb0);
    } else if (tid == 1) {
        bulk_cp(sbase + 53248, (const char*)&g_WA[l][0], 34816, mb0);
    } else if (tid == 2) {
        bulk_cp(sbase + 27136, blo, 26112, mb1);
    } else if (tid >= 64 && tid < 192) {
        fs[tid - 64] = __ldg(fw3 + tid - 64);
    } else if (tid >= 192) {
        int c = tid - 192;
        pb[c] = cb[c];
        pb[64 + c] = bag[c];
        pb[128 + c] = bab[c];
        pb[192 + c] = bbg[c];
        pb[256 + c] = bbb[c];
    }
    __syncthreads();   // fs/pb visible

    // ---- GEMM: fused pass0 (bh x {Wh,Wl}) + pass1 (bl x Wh) ----
    int wm = w & 1, wn = w >> 1;
    unsigned laneoff = ((lane & 15) * 136 + (lane >> 4) * 8) * 2;
    int bloff = (lane >> 2) * 68 + (lane & 3);
    const unsigned* WpH = (const unsigned*)(smem + 53248);
    const unsigned* WpL = (const unsigned*)(smem + 70656);
    float d[3][2][4];
#pragma unroll
    for (int mt = 0; mt < 3; mt++)
#pragma unroll
        for (int nt = 0; nt < 2; nt++)
#pragma unroll
            for (int fr = 0; fr < 4; fr++) d[mt][nt][fr] = 0.f;

#pragma unroll 1
    for (int p = 0; p < 2; p++) {
        mbar_wait(p ? mb1 : mb0);
        unsigned abase = sbase + (p ? 27136u : 1024u) + laneoff +
                         (unsigned)(wm * 48 * 272);
#pragma unroll
        for (int ks = 0; ks < 8; ks++) {
            int k0 = ks * 16;
            unsigned bfrH[2][2], bfrL[2][2];
#pragma unroll
            for (int nt = 0; nt < 2; nt++) {
                int idx = (wn * 16 + nt * 8) * 68 + (k0 >> 1) + bloff;
                bfrH[nt][0] = WpH[idx];
                bfrH[nt][1] = WpH[idx + 4];
                if (p == 0) {
                    bfrL[nt][0] = WpL[idx];
                    bfrL[nt][1] = WpL[idx + 4];
                }
            }
#pragma unroll
            for (int mt = 0; mt < 3; mt++) {
                unsigned afr[4];
                ldmx4(afr, abase + mt * (16 * 272) + k0 * 2);
                mma16816(d[mt][0], afr, bfrH[0]);
                mma16816(d[mt][1], afr, bfrH[1]);
                if (p == 0) {
                    mma16816(d[mt][0], afr, bfrL[0]);
                    mma16816(d[mt][1], afr, bfrL[1]);
                }
            }
        }
    }

    // ---- filter logits (reads sBh+sBl before reuse) ----
    if (tid < 96) {
        int row = tid;
        int a_ = row / 12, m = row - a_ * 12;
        int nbr = nbrl[(bn0 + a_) * 12 + m];
        nb[row] = nbr;
        const __nv_bfloat16* ph = sBh + row * 136;
        const __nv_bfloat16* pl = sBl + row * 136;
        float acc2 = 0.f;
#pragma unroll
        for (int k = 0; k < 128; k += 8) {
            uint4 uh = *(const uint4*)(ph + k);
            uint4 ul = *(const uint4*)(pl + k);
            float2 h0 = bf2(uh.x), h1 = bf2(uh.y), h2 = bf2(uh.z),
                   h3 = bf2(uh.w);
            float2 q0 = bf2(ul.x), q1 = bf2(ul.y), q2 = bf2(ul.z),
                   q3 = bf2(ul.w);
            acc2 += (h0.x + q0.x) * fs[k] + (h0.y + q0.y) * fs[k + 1] +
                    (h1.x + q1.x) * fs[k + 2] + (h1.y + q1.y) * fs[k + 3] +
                    (h2.x + q2.x) * fs[k + 4] + (h2.y + q2.y) * fs[k + 5] +
                    (h3.x + q3.x) * fs[k + 6] + (h3.y + q3.y) * fs[k + 7];
        }
        ft[row] = acc2 + S1r[bn0 + a_] + S2r[b * 1024 + nbr] + fb[0];
    }
    __syncthreads();

    // ---- stage y1/y2 (coalesced) + softmax over m ----
    for (int i = tid; i < 1536; i += 256) {
        int row = i >> 4, q = i & 15;
        *(float4*)(y2s + row * 64 + q * 4) =
            *(const float4*)(Y2r + (b * 1024 + nb[row]) * 64 + q * 4);
    }
    if (tid < 128) {
        int a = tid >> 4, q = tid & 15;
        *(float4*)(y1s + a * 64 + q * 4) =
            *(const float4*)(Y1r + (bn0 + a) * 64 + q * 4);
    }
    if (w == 7 && lane < 8) {
        int base = lane * 12;
        float mx = -1e30f;
#pragma unroll
        for (int m = 0; m < 12; m++) mx = fmaxf(mx, ft[base + m]);
        float s = 0.f;
#pragma unroll
        for (int m = 0; m < 12; m++) s += expf(ft[base + m] - mx);
        float inv = 1.f / (12.f * s);
#pragma unroll
        for (int m = 0; m < 12; m++)
            ft[base + m] = expf(ft[base + m] - mx) * inv;
    }
    __syncthreads();

    // ---- epilogue: frag + y1 + y2 + cb -> BN -> relu -> Cs ----
#pragma unroll
    for (int mt = 0; mt < 3; mt++) {
        int r0 = wm * 48 + mt * 16 + (lane >> 2);
#pragma unroll
        for (int nt = 0; nt < 2; nt++) {
            int c0 = wn * 16 + nt * 8 + (lane & 3) * 2;
#pragma unroll
            for (int fr = 0; fr < 4; fr++) {
                int row = r0 + (fr >> 1) * 8;
                int c = c0 + (fr & 1);
                int a_ = row / 12;
                float v = d[mt][nt][fr] + y1s[a_ * 64 + c] +
                          y2s[row * 64 + c] + pb[c];
                v = fmaxf(pb[64 + c] * (v * BN_ALPHA) + pb[128 + c], 0.f);
                Cs[row * 65 + c] = v;
            }
        }
    }
    __syncthreads();

    // ---- weighted mean, BN, residual relu; stash xn ----
#pragma unroll
    for (int q = 0; q < 2; q++) {
        int idx = tid + 256 * q;   // < 512 = 8*64
        int a_ = idx >> 6, c = idx & 63;
        float s = 0.f;
#pragma unroll
        for (int m = 0; m < 12; m++)
            s += ft[a_ * 12 + m] * Cs[(a_ * 12 + m) * 65 + c];
        s = pb[192 + c] * (s * BN_ALPHA) + pb[256 + c];
        int gi = (bn0 + a_) * 64 + c;
        float xv = fmaxf(Xc[gi] + s, 0.f);
        Xn[gi] = xv;
        xb[a_ * 68 + c] = xv;
    }
    __syncthreads();

    // ---- fused next-layer projection (8 atoms, write buffer ywr) ----
    if (do_proj && tid < 130) {
        proj8(xb, bn0, 0, tid, ywr, cwn, fwn);
    }
}

// ---------------------------------------------------------------------------
__global__ void __launch_bounds__(256) final_k(const int* __restrict__ tix,
                                               const float* __restrict__ dw,
                                               const float* __restrict__ db,
                                               float* __restrict__ out) {
    __shared__ float cs[64 * 68];
    __shared__ float wd[64 * 65];
    int b = blockIdx.x, tid = threadIdx.x;
    for (int t = tid; t < 4096; t += 256) {
        int k = t >> 6, f = t & 63;
        wd[k * 65 + f] = dw[t];
    }
    for (int t = tid; t < 1024; t += 256) {
        int j = t >> 4, q = t & 15;
        int ti = tix[b * 64 + j];
        float4 v = *(const float4*)(g_X1 + (b * 1024 + ti) * 64 + q * 4);
        v.x = fmaxf(v.x, 0.f);
        v.y = fmaxf(v.y, 0.f);
        v.z = fmaxf(v.z, 0.f);
        v.w = fmaxf(v.w, 0.f);
        *(float4*)(cs + j * 68 + q * 4) = v;
    }
    __syncthreads();
    for (int t = tid; t < 4096; t += 256) {
        int j = t >> 6, f = t & 63;
        float acc = db[f];
#pragma unroll 8
        for (int k = 0; k < 64; k++) acc += cs[j * 68 + k] * wd[k * 65 + f];
        out[b * 4096 + t] = fmaxf(acc, 0.f);
    }
}

// ---------------------------------------------------------------------------
extern "C" void kernel_launch(void* const* d_in, const int* in_sizes, int n_in,
                              void* d_out, int out_size) {
    const int* atom_types = (const int*)d_in[0];
    const float* bond = (const float*)d_in[1];
    const int* nbrl = (const int*)d_in[2];
    const int* tix = (const int*)d_in[3];
    const float* emb = (const float*)d_in[4];
    const float* core_w = (const float*)d_in[5];
    const float* core_b = (const float*)d_in[6];
    const float* filt_w = (const float*)d_in[7];
    const float* filt_b = (const float*)d_in[8];
    const float* bna_g = (const float*)d_in[9];
    const float* bna_b = (const float*)d_in[10];
    const float* bnb_g = (const float*)d_in[11];
    const float* bnb_b = (const float*)d_in[12];
    const float* dw = (const float*)d_in[13];
    const float* db = (const float*)d_in[14];
    float* out = (float*)d_out;

    cudaFuncSetAttribute(conv_k, cudaFuncAttributeMaxDynamicSharedMemorySize,
                         CONV_SMEM);

    prep_w_k<<<3, 256>>>(core_w);
    prep_bond_k<<<1024, 256>>>(bond);
    embed_proj_k<<<1024, 256>>>(atom_types, emb, core_w, filt_w);
    for (int l = 0; l < 3; l++) {
        int flip = l & 1;
        int yrd = l & 1;
        int ywr = (l + 1) & 1;
        int do_proj = (l < 2) ? 1 : 0;
        const float* cwn = core_w + (l + 1 < 3 ? (l + 1) : l) * 256 * 64;
        const float* fwn = filt_w + (l + 1 < 3 ? (l + 1) : l) * 256;
        conv_k<<<2048, 256, CONV_SMEM>>>(
            l, flip, yrd, ywr, nbrl, filt_w + l * 256 + 128, core_b + l * 64,
            filt_b + l, bna_g + l * 64, bna_b + l * 64, bnb_g + l * 64,
            bnb_b + l * 64, do_proj, cwn, fwn);
    }
    final_k<<<16, 256>>>(tix, dw, db, out);
}

// round 12
// speedup vs baseline: 1.7386x; 1.0365x over previous
#include <cuda_runtime.h>
#include <cuda_bf16.h>

// ---------------------------------------------------------------------------
// CGCNN: B=16, N=1024, M=12, F=64, BF=128, N_CONV=3, VOCAB=100
// total@W = x@W1 + gather(x@W2) + bond@W3 ; proj fused into conv/embed.
// Bond GEMM via mma.sync m16n8k16 bf16 hi/lo split: bh*(Wh+Wl) + bl*Wh.
// conv: 8 atoms/block (96 rows), 256 threads, 2 blocks/SM.
// R12: filter logits precomputed in prep_bond (fp32), ft/softmax moved
// pre-GEMM (overlaps TMA), W stored in mma-fragment order (LDS.64 loads).
// ---------------------------------------------------------------------------

#define BN_ALPHA 0.99950037f   // 1/sqrt(1+1e-3)

__device__ float g_X0[16 * 1024 * 64];
__device__ float g_X1[16 * 1024 * 64];
__device__ float g_Y1[2][16 * 1024 * 64];
__device__ float g_Y2[2][16 * 1024 * 64];
__device__ float g_S1[2][16 * 1024];
__device__ float g_S2[2][16 * 1024];
__device__ float g_FL[3][16 * 1024 * 12];                // bond @ fw3 (fp32)
__device__ __nv_bfloat16 g_WA[3][16384];                 // W frag-order hi|lo
__device__ __nv_bfloat16 g_BB[1024ull * 2 * 192 * 136];  // bond hi/lo blobs

// ---- mbarrier / bulk helpers ----------------------------------------------
__device__ __forceinline__ void mbar_init(unsigned m, unsigned c) {
    asm volatile("mbarrier.init.shared.b64 [%0], %1;" ::"r"(m), "r"(c)
                 : "memory");
}
__device__ __forceinline__ void mbar_expect(unsigned m, unsigned b) {
    asm volatile("mbarrier.arrive.expect_tx.shared.b64 _, [%0], %1;" ::"r"(m),
                 "r"(b)
                 : "memory");
}
__device__ __forceinline__ void mbar_wait(unsigned m) {
    asm volatile(
        "{\n\t.reg .pred P;\n\tW%=:\n\t"
        "mbarrier.try_wait.parity.acquire.cta.shared::cta.b64 P, [%0], 0;\n\t"
        "@!P bra W%=;\n\t}" ::"r"(m)
        : "memory");
}
__device__ __forceinline__ void bulk_cp(unsigned d, const void* s, unsigned b,
                                        unsigned m) {
    asm volatile(
        "cp.async.bulk.shared::cta.global.mbarrier::complete_tx::bytes "
        "[%0], [%1], %2, [%3];" ::"r"(d),
        "l"(s), "r"(b), "r"(m)
        : "memory");
}

// ---- tensor-core helpers (sm_80+ PTX) -------------------------------------
__device__ __forceinline__ void mma16816(float* d, const unsigned* a,
                                         const unsigned* b) {
    asm volatile(
        "mma.sync.aligned.m16n8k16.row.col.f32.bf16.bf16.f32 "
        "{%0,%1,%2,%3}, {%4,%5,%6,%7}, {%8,%9}, {%0,%1,%2,%3};"
        : "+f"(d[0]), "+f"(d[1]), "+f"(d[2]), "+f"(d[3])
        : "r"(a[0]), "r"(a[1]), "r"(a[2]), "r"(a[3]), "r"(b[0]), "r"(b[1]));
}
__device__ __forceinline__ void ldmx4(unsigned* a, unsigned addr) {
    asm volatile(
        "ldmatrix.sync.aligned.m8n8.x4.shared.b16 {%0,%1,%2,%3}, [%4];"
        : "=r"(a[0]), "=r"(a[1]), "=r"(a[2]), "=r"(a[3])
        : "r"(addr));
}

// ---------------------------------------------------------------------------
// prep_w_k: W hi/lo in mma B-fragment order.
// word t (bf16x2): r=t&1, lane=(t>>1)&31, nt=(t>>6)&1, wn=(t>>7)&3, ks=t>>9;
// n = wn*16+nt*8+(lane>>2); k = ks*16+(lane&3)*2+r*8 (pair k,k+1).
// grid 3 x 256.
// ---------------------------------------------------------------------------
__global__ void __launch_bounds__(256) prep_w_k(const float* __restrict__ cw) {
    int l = blockIdx.x;
    const float* W = cw + l * 256 * 64 + 128 * 64;   // [k][n]
    __nv_bfloat162* outp = (__nv_bfloat162*)g_WA[l];
    for (int t = threadIdx.x; t < 4096; t += 256) {
        int r = t & 1;
        int lane = (t >> 1) & 31;
        int nt = (t >> 6) & 1, wn = (t >> 7) & 3, ks = t >> 9;
        int n = wn * 16 + nt * 8 + (lane >> 2);
        int k = ks * 16 + (lane & 3) * 2 + r * 8;
        float w0 = W[k * 64 + n], w1 = W[(k + 1) * 64 + n];
        __nv_bfloat16 h0 = __float2bfloat16(w0);
        __nv_bfloat16 h1 = __float2bfloat16(w1);
        __nv_bfloat162 hh, ll;
        hh.x = h0;
        hh.y = h1;
        ll.x = __float2bfloat16(w0 - __bfloat162float(h0));
        ll.y = __float2bfloat16(w1 - __bfloat162float(h1));
        outp[t] = hh;
        outp[4096 + t] = ll;
    }
}

// ---------------------------------------------------------------------------
// prep_bond_k: per 16-atom tile emit [hi 192x136 | lo 192x136] bf16 +
// fp32 filter logits for all 3 layers (shfl-reduced over the 16 lanes that
// hold one row). grid 1024 x 256.
// ---------------------------------------------------------------------------
__global__ void __launch_bounds__(256) prep_bond_k(
    const float* __restrict__ bond, const float* __restrict__ filt_w) {
    __shared__ float sfw[384];
    for (int t = threadIdx.x; t < 384; t += 256) {
        int l = t >> 7, q = t & 127;
        sfw[t] = filt_w[l * 256 + 128 + q];
    }
    __syncthreads();
    size_t tile = blockIdx.x;
    const float* src = bond + tile * 192 * 128;
    __nv_bfloat16* dh = g_BB + tile * 52224;
    __nv_bfloat16* dl = dh + 26112;
    for (int i = threadIdx.x; i < 192 * 16; i += 256) {
        int row = i >> 4, q = i & 15;
        const float* s = src + row * 128 + q * 8;
        float4 v0 = *(const float4*)s;
        float4 v1 = *(const float4*)(s + 4);
        float v[8] = {v0.x, v0.y, v0.z, v0.w, v1.x, v1.y, v1.z, v1.w};
        unsigned hu[4], lu[4];
#pragma unroll
        for (int p = 0; p < 4; p++) {
            __nv_bfloat16 h0 = __float2bfloat16(v[2 * p]);
            __nv_bfloat16 h1 = __float2bfloat16(v[2 * p + 1]);
            __nv_bfloat162 hh, ll;
            hh.x = h0;
            hh.y = h1;
            ll.x = __float2bfloat16(v[2 * p] - __bfloat162float(h0));
            ll.y = __float2bfloat16(v[2 * p + 1] - __bfloat162float(h1));
            hu[p] = reinterpret_cast<unsigned&>(hh);
            lu[p] = reinterpret_cast<unsigned&>(ll);
        }
        *(uint4*)(dh + row * 136 + q * 8) =
            make_uint4(hu[0], hu[1], hu[2], hu[3]);
        *(uint4*)(dl + row * 136 + q * 8) =
            make_uint4(lu[0], lu[1], lu[2], lu[3]);
        // filter logits: partial dots, reduce over the 16 lanes of this row
        float p0 = 0.f, p1 = 0.f, p2 = 0.f;
#pragma unroll
        for (int p = 0; p < 8; p++) {
            float vv = v[p];
            p0 += vv * sfw[q * 8 + p];
            p1 += vv * sfw[128 + q * 8 + p];
            p2 += vv * sfw[256 + q * 8 + p];
        }
#pragma unroll
        for (int off = 8; off; off >>= 1) {
            p0 += __shfl_xor_sync(0xFFFFFFFFu, p0, off);
            p1 += __shfl_xor_sync(0xFFFFFFFFu, p1, off);
            p2 += __shfl_xor_sync(0xFFFFFFFFu, p2, off);
        }
        if ((threadIdx.x & 15) == 0) {
            size_t gr = tile * 192 + row;
            g_FL[0][gr] = p0;
            g_FL[1][gr] = p1;
            g_FL[2][gr] = p2;
        }
    }
}

// ---------------------------------------------------------------------------
// proj8 (vectorized): 8 rows of x (smem, stride 68) -> Y1/Y2/S1/S2 buffer yb
// ---------------------------------------------------------------------------
__device__ __forceinline__ void proj8(const float* __restrict__ xs, int bn0,
                                      int r0, int c2, int yb,
                                      const float* __restrict__ cwn,
                                      const float* __restrict__ fwn) {
    const float* wp;
    int st;
    if (c2 < 64) {
        wp = cwn + c2;
        st = 64;
    } else if (c2 < 128) {
        wp = cwn + 64 * 64 + (c2 - 64);
        st = 64;
    } else {
        wp = fwn + (c2 - 128) * 64;
        st = 1;
    }
    float acc[8] = {0.f, 0.f, 0.f, 0.f, 0.f, 0.f, 0.f, 0.f};
#pragma unroll 2
    for (int k = 0; k < 64; k += 4) {
        float4 xv[8];
#pragma unroll
        for (int rr = 0; rr < 8; rr++)
            xv[rr] = *(const float4*)(xs + (r0 + rr) * 68 + k);
#pragma unroll
        for (int j = 0; j < 4; j++) {
            float wv = __ldg(wp + (k + j) * st);
#pragma unroll
            for (int rr = 0; rr < 8; rr++)
                acc[rr] += ((const float*)&xv[rr])[j] * wv;
        }
    }
    if (c2 < 64) {
#pragma unroll
        for (int rr = 0; rr < 8; rr++)
            g_Y1[yb][(bn0 + r0 + rr) * 64 + c2] = acc[rr];
    } else if (c2 < 128) {
#pragma unroll
        for (int rr = 0; rr < 8; rr++)
            g_Y2[yb][(bn0 + r0 + rr) * 64 + (c2 - 64)] = acc[rr];
    } else if (c2 == 128) {
#pragma unroll
        for (int rr = 0; rr < 8; rr++) g_S1[yb][bn0 + r0 + rr] = acc[rr];
    } else {
#pragma unroll
        for (int rr = 0; rr < 8; rr++) g_S2[yb][bn0 + r0 + rr] = acc[rr];
    }
}

__global__ void __launch_bounds__(256) embed_proj_k(
    const int* __restrict__ types, const float* __restrict__ emb,
    const float* __restrict__ cwn, const float* __restrict__ fwn) {
    __shared__ float xs[16 * 68];
    int tid = threadIdx.x;
    int bn0 = blockIdx.x * 16;
    {
        int r = tid >> 4, q = tid & 15;
        int t = types[bn0 + r];
        float4 v = *(const float4*)(emb + t * 64 + q * 4);
        *(float4*)(xs + r * 68 + q * 4) = v;
        *(float4*)(g_X0 + (bn0 + r) * 64 + q * 4) = v;
    }
    __syncthreads();
    if (tid < 130) {
        proj8(xs, bn0, 0, tid, 0, cwn, fwn);
        proj8(xs, bn0, 8, tid, 0, cwn, fwn);
    }
}

// ---------------------------------------------------------------------------
// conv_k: one block = 8 atoms (96 rows), 256 threads, 2 blocks/SM.
// 8 warps = 2 row-groups (48) x 4 col-groups (16).
// Pre-GEMM (overlaps TMA): nb, ft from g_FL+S1+S2, softmax.
// GEMM: fused pass0 (bh x {Wh,Wl}) + pass1 (bl x Wh); W frag-order LDS.64.
// smem (bytes): 16,24 mbars | 1024 sBh(26112) | 27136 sBl(26112) |
// 53248 sW(32768: hi|lo) | 86016 ft(384) | 86400 nb(384) | 86784 xb(2176) |
// 88960 pb(1280) | 90240 y1s(2048) -> 92288
// reuse after GEMM: y2s = sBh, Cs = sBl.
// ---------------------------------------------------------------------------
#define CONV_SMEM 92288

__global__ void __launch_bounds__(256, 2) conv_k(
    int l, int flip, int yrd, int ywr, const int* __restrict__ nbrl,
    const float* __restrict__ cb, const float* __restrict__ fb,
    const float* __restrict__ bag, const float* __restrict__ bab,
    const float* __restrict__ bbg, const float* __restrict__ bbb, int do_proj,
    const float* __restrict__ cwn, const float* __restrict__ fwn) {
    extern __shared__ char smem[];
    unsigned sbase = (unsigned)__cvta_generic_to_shared(smem);
    float* ft = (float*)(smem + 86016);
    int* nb = (int*)(smem + 86400);
    float* xb = (float*)(smem + 86784);
    float* pb = (float*)(smem + 88960);
    float* y1s = (float*)(smem + 90240);
    float* y2s = (float*)(smem + 1024);    // reuse sBh after GEMM
    float* Cs = (float*)(smem + 27136);    // reuse sBl after GEMM
    unsigned mb0 = sbase + 16, mb1 = sbase + 24;

    const float* Xc = flip ? g_X1 : g_X0;
    float* Xn = flip ? g_X0 : g_X1;
    const float* Y1r = g_Y1[yrd];
    const float* Y2r = g_Y2[yrd];
    const float* S1r = g_S1[yrd];
    const float* S2r = g_S2[yrd];

    int tid = threadIdx.x;
    int lane = tid & 31, w = tid >> 5;
    int bn0 = blockIdx.x * 8;          // 8 atoms per block
    int b = bn0 >> 10;

    if (tid == 0) {
        mbar_init(mb0, 1);
        mbar_init(mb1, 1);
        mbar_expect(mb0, 26112 + 32768);
        mbar_expect(mb1, 26112);
    }
    __syncthreads();

    size_t tile = blockIdx.x >> 1;
    unsigned half = blockIdx.x & 1;
    const char* bh = (const char*)(g_BB + tile * 52224 + half * 96 * 136);
    const char* blo =
        (const char*)(g_BB + tile * 52224 + 26112 + half * 96 * 136);

    if (tid == 0) {
        bulk_cp(sbase + 1024, bh, 26112, mb0);
    } else if (tid == 1) {
        bulk_cp(sbase + 53248, (const char*)&g_WA[l][0], 32768, mb0);
    } else if (tid == 2) {
        bulk_cp(sbase + 27136, blo, 26112, mb1);
    } else if (tid >= 192) {
        int c = tid - 192;
        pb[c] = cb[c];
        pb[64 + c] = bag[c];
        pb[128 + c] = bab[c];
        pb[192 + c] = bbg[c];
        pb[256 + c] = bbb[c];
    }

    // ---- pre-GEMM: nb + ft (precomputed logits) — overlaps TMA ----
    if (tid < 96) {
        int row = tid;
        int a_ = row / 12, m = row - a_ * 12;
        int nbr = nbrl[(bn0 + a_) * 12 + m];
        nb[row] = nbr;
        ft[row] = __ldg(&g_FL[l][(size_t)blockIdx.x * 96 + row]) +
                  S1r[bn0 + a_] + S2r[b * 1024 + nbr] + fb[0];
    }
    __syncthreads();
    if (tid < 8) {   // softmax over m (folds the 1/12 mean)
        int base = tid * 12;
        float mx = -1e30f;
#pragma unroll
        for (int m = 0; m < 12; m++) mx = fmaxf(mx, ft[base + m]);
        float s = 0.f;
#pragma unroll
        for (int m = 0; m < 12; m++) s += expf(ft[base + m] - mx);
        float inv = 1.f / (12.f * s);
#pragma unroll
        for (int m = 0; m < 12; m++)
            ft[base + m] = expf(ft[base + m] - mx) * inv;
    }

    // ---- GEMM: fused pass0 (bh x {Wh,Wl}) + pass1 (bl x Wh) ----
    int wm = w & 1, wn = w >> 1;
    unsigned laneoff = ((lane & 15) * 136 + (lane >> 4) * 8) * 2;
    const uint2* WH = (const uint2*)(smem + 53248);
    const uint2* WL = (const uint2*)(smem + 53248 + 16384);
    float d[3][2][4];
#pragma unroll
    for (int mt = 0; mt < 3; mt++)
#pragma unroll
        for (int nt = 0; nt < 2; nt++)
#pragma unroll
            for (int fr = 0; fr < 4; fr++) d[mt][nt][fr] = 0.f;

#pragma unroll 1
    for (int p = 0; p < 2; p++) {
        mbar_wait(p ? mb1 : mb0);
        unsigned abase = sbase + (p ? 27136u : 1024u) + laneoff +
                         (unsigned)(wm * 48 * 272);
#pragma unroll
        for (int ks = 0; ks < 8; ks++) {
            int k0 = ks * 16;
            unsigned bfrH[2][2], bfrL[2][2];
#pragma unroll
            for (int nt = 0; nt < 2; nt++) {
                uint2 vH = WH[(ks * 8 + wn * 2 + nt) * 32 + lane];
                bfrH[nt][0] = vH.x;
                bfrH[nt][1] = vH.y;
                if (p == 0) {
                    uint2 vL = WL[(ks * 8 + wn * 2 + nt) * 32 + lane];
                    bfrL[nt][0] = vL.x;
                    bfrL[nt][1] = vL.y;
                }
            }
#pragma unroll
            for (int mt = 0; mt < 3; mt++) {
                unsigned afr[4];
                ldmx4(afr, abase + mt * (16 * 272) + k0 * 2);
                mma16816(d[mt][0], afr, bfrH[0]);
                mma16816(d[mt][1], afr, bfrH[1]);
                if (p == 0) {
                    mma16816(d[mt][0], afr, bfrL[0]);
                    mma16816(d[mt][1], afr, bfrL[1]);
                }
            }
        }
    }
    __syncthreads();   // all GEMM reads of sBh/sBl done

    // ---- stage y1/y2 (coalesced) into reused smem ----
    for (int i = tid; i < 1536; i += 256) {
        int row = i >> 4, q = i & 15;
        *(float4*)(y2s + row * 64 + q * 4) =
            *(const float4*)(Y2r + (b * 1024 + nb[row]) * 64 + q * 4);
    }
    if (tid < 128) {
        int a = tid >> 4, q = tid & 15;
        *(float4*)(y1s + a * 64 + q * 4) =
            *(const float4*)(Y1r + (bn0 + a) * 64 + q * 4);
    }
    __syncthreads();

    // ---- epilogue: frag + y1 + y2 + cb -> BN -> relu -> Cs ----
#pragma unroll
    for (int mt = 0; mt < 3; mt++) {
        int r0 = wm * 48 + mt * 16 + (lane >> 2);
#pragma unroll
        for (int nt = 0; nt < 2; nt++) {
            int c0 = wn * 16 + nt * 8 + (lane & 3) * 2;
#pragma unroll
            for (int fr = 0; fr < 4; fr++) {
                int row = r0 + (fr >> 1) * 8;
                int c = c0 + (fr & 1);
                int a_ = row / 12;
                float v = d[mt][nt][fr] + y1s[a_ * 64 + c] +
                          y2s[row * 64 + c] + pb[c];
                v = fmaxf(pb[64 + c] * (v * BN_ALPHA) + pb[128 + c], 0.f);
                Cs[row * 65 + c] = v;
            }
        }
    }
    __syncthreads();

    // ---- weighted mean, BN, residual relu; stash xn ----
#pragma unroll
    for (int q = 0; q < 2; q++) {
        int idx = tid + 256 * q;   // < 512 = 8*64
        int a_ = idx >> 6, c = idx & 63;
        float s = 0.f;
#pragma unroll
        for (int m = 0; m < 12; m++)
            s += ft[a_ * 12 + m] * Cs[(a_ * 12 + m) * 65 + c];
        s = pb[192 + c] * (s * BN_ALPHA) + pb[256 + c];
        int gi = (bn0 + a_) * 64 + c;
        float xv = fmaxf(Xc[gi] + s, 0.f);
        Xn[gi] = xv;
        xb[a_ * 68 + c] = xv;
    }
    __syncthreads();

    // ---- fused next-layer projection (8 atoms, write buffer ywr) ----
    if (do_proj && tid < 130) {
        proj8(xb, bn0, 0, tid, ywr, cwn, fwn);
    }
}

// ---------------------------------------------------------------------------
__global__ void __launch_bounds__(256) final_k(const int* __restrict__ tix,
                                               const float* __restrict__ dw,
                                               const float* __restrict__ db,
                                               float* __restrict__ out) {
    __shared__ float cs[64 * 68];
    __shared__ float wd[64 * 65];
    int b = blockIdx.x, tid = threadIdx.x;
    for (int t = tid; t < 4096; t += 256) {
        int k = t >> 6, f = t & 63;
        wd[k * 65 + f] = dw[t];
    }
    for (int t = tid; t < 1024; t += 256) {
        int j = t >> 4, q = t & 15;
        int ti = tix[b * 64 + j];
        float4 v = *(const float4*)(g_X1 + (b * 1024 + ti) * 64 + q * 4);
        v.x = fmaxf(v.x, 0.f);
        v.y = fmaxf(v.y, 0.f);
        v.z = fmaxf(v.z, 0.f);
        v.w = fmaxf(v.w, 0.f);
        *(float4*)(cs + j * 68 + q * 4) = v;
    }
    __syncthreads();
    for (int t = tid; t < 4096; t += 256) {
        int j = t >> 6, f = t & 63;
        float acc = db[f];
#pragma unroll 8
        for (int k = 0; k < 64; k++) acc += cs[j * 68 + k] * wd[k * 65 + f];
        out[b * 4096 + t] = fmaxf(acc, 0.f);
    }
}

// ---------------------------------------------------------------------------
extern "C" void kernel_launch(void* const* d_in, const int* in_sizes, int n_in,
                              void* d_out, int out_size) {
    const int* atom_types = (const int*)d_in[0];
    const float* bond = (const float*)d_in[1];
    const int* nbrl = (const int*)d_in[2];
    const int* tix = (const int*)d_in[3];
    const float* emb = (const float*)d_in[4];
    const float* core_w = (const float*)d_in[5];
    const float* core_b = (const float*)d_in[6];
    const float* filt_w = (const float*)d_in[7];
    const float* filt_b = (const float*)d_in[8];
    const float* bna_g = (const float*)d_in[9];
    const float* bna_b = (const float*)d_in[10];
    const float* bnb_g = (const float*)d_in[11];
    const float* bnb_b = (const float*)d_in[12];
    const float* dw = (const float*)d_in[13];
    const float* db = (const float*)d_in[14];
    float* out = (float*)d_out;

    cudaFuncSetAttribute(conv_k, cudaFuncAttributeMaxDynamicSharedMemorySize,
                         CONV_SMEM);

    prep_w_k<<<3, 256>>>(core_w);
    prep_bond_k<<<1024, 256>>>(bond, filt_w);
    embed_proj_k<<<1024, 256>>>(atom_types, emb, core_w, filt_w);
    for (int l = 0; l < 3; l++) {
        int flip = l & 1;
        int yrd = l & 1;
        int ywr = (l + 1) & 1;
        int do_proj = (l < 2) ? 1 : 0;
        const float* cwn = core_w + (l + 1 < 3 ? (l + 1) : l) * 256 * 64;
        const float* fwn = filt_w + (l + 1 < 3 ? (l + 1) : l) * 256;
        conv_k<<<2048, 256, CONV_SMEM>>>(
            l, flip, yrd, ywr, nbrl, core_b + l * 64, filt_b + l,
            bna_g + l * 64, bna_b + l * 64, bnb_g + l * 64, bnb_b + l * 64,
            do_proj, cwn, fwn);
    }
    final_k<<<16, 256>>>(tix, dw, db, out);
}

// round 13
// speedup vs baseline: 2.2183x; 1.2759x over previous
#include <cuda_runtime.h>
#include <cuda_fp16.h>

// ---------------------------------------------------------------------------
// CGCNN: B=16, N=1024, M=12, F=64, BF=128, N_CONV=3, VOCAB=100
// total@W = x@W1 + gather(x@W2) + bond@W3 ; proj fused into conv/embed.
// R13: fp16 split. Bond stored as SINGLE fp16 image (err ~2^-12); W as fp16
// hi+lo fragment-order pair. C = bond_h @ (Wh + Wl)  -> one GEMM pass.
// conv: 8 atoms/block (96 rows), 256 threads, 3 blocks/SM.
// Filter logits precomputed exact-fp32 in prep_bond (g_FL).
// ---------------------------------------------------------------------------

#define BN_ALPHA 0.99950037f   // 1/sqrt(1+1e-3)

__device__ float g_X0[16 * 1024 * 64];
__device__ float g_X1[16 * 1024 * 64];
__device__ float g_Y1[2][16 * 1024 * 64];
__device__ float g_Y2[2][16 * 1024 * 64];
__device__ float g_S1[2][16 * 1024];
__device__ float g_S2[2][16 * 1024];
__device__ float g_FL[3][16 * 1024 * 12];         // bond @ fw3 (fp32, exact)
__device__ __half g_WA[3][16384];                 // W frag-order [hi|lo] fp16
__device__ __half g_BB[1024ull * 192 * 136];      // bond fp16 blobs, 52KB/tile

// ---- mbarrier / bulk helpers ----------------------------------------------
__device__ __forceinline__ void mbar_init(unsigned m, unsigned c) {
    asm volatile("mbarrier.init.shared.b64 [%0], %1;" ::"r"(m), "r"(c)
                 : "memory");
}
__device__ __forceinline__ void mbar_expect(unsigned m, unsigned b) {
    asm volatile("mbarrier.arrive.expect_tx.shared.b64 _, [%0], %1;" ::"r"(m),
                 "r"(b)
                 : "memory");
}
__device__ __forceinline__ void mbar_wait(unsigned m) {
    asm volatile(
        "{\n\t.reg .pred P;\n\tW%=:\n\t"
        "mbarrier.try_wait.parity.acquire.cta.shared::cta.b64 P, [%0], 0;\n\t"
        "@!P bra W%=;\n\t}" ::"r"(m)
        : "memory");
}
__device__ __forceinline__ void bulk_cp(unsigned d, const void* s, unsigned b,
                                        unsigned m) {
    asm volatile(
        "cp.async.bulk.shared::cta.global.mbarrier::complete_tx::bytes "
        "[%0], [%1], %2, [%3];" ::"r"(d),
        "l"(s), "r"(b), "r"(m)
        : "memory");
}

// ---- tensor-core helpers (sm_80+ PTX) -------------------------------------
__device__ __forceinline__ void mma16816(float* d, const unsigned* a,
                                         const unsigned* b) {
    asm volatile(
        "mma.sync.aligned.m16n8k16.row.col.f32.f16.f16.f32 "
        "{%0,%1,%2,%3}, {%4,%5,%6,%7}, {%8,%9}, {%0,%1,%2,%3};"
        : "+f"(d[0]), "+f"(d[1]), "+f"(d[2]), "+f"(d[3])
        : "r"(a[0]), "r"(a[1]), "r"(a[2]), "r"(a[3]), "r"(b[0]), "r"(b[1]));
}
__device__ __forceinline__ void ldmx4(unsigned* a, unsigned addr) {
    asm volatile(
        "ldmatrix.sync.aligned.m8n8.x4.shared.b16 {%0,%1,%2,%3}, [%4];"
        : "=r"(a[0]), "=r"(a[1]), "=r"(a[2]), "=r"(a[3])
        : "r"(addr));
}

// ---------------------------------------------------------------------------
// prep_w_k: W fp16 hi/lo in mma B-fragment order.
// word t (half2): r=t&1, lane=(t>>1)&31, nt=(t>>6)&1, wn=(t>>7)&3, ks=t>>9;
// n = wn*16+nt*8+(lane>>2); k = ks*16+(lane&3)*2+r*8 (pair k,k+1).
// grid 3 x 256.
// ---------------------------------------------------------------------------
__global__ void __launch_bounds__(256) prep_w_k(const float* __restrict__ cw) {
    int l = blockIdx.x;
    const float* W = cw + l * 256 * 64 + 128 * 64;   // [k][n]
    __half2* outp = (__half2*)g_WA[l];
    for (int t = threadIdx.x; t < 4096; t += 256) {
        int r = t & 1;
        int lane = (t >> 1) & 31;
        int nt = (t >> 6) & 1, wn = (t >> 7) & 3, ks = t >> 9;
        int n = wn * 16 + nt * 8 + (lane >> 2);
        int k = ks * 16 + (lane & 3) * 2 + r * 8;
        float w0 = W[k * 64 + n], w1 = W[(k + 1) * 64 + n];
        __half h0 = __float2half(w0);
        __half h1 = __float2half(w1);
        __half2 hh, ll;
        hh.x = h0;
        hh.y = h1;
        ll.x = __float2half(w0 - __half2float(h0));
        ll.y = __float2half(w1 - __half2float(h1));
        outp[t] = hh;
        outp[4096 + t] = ll;
    }
}

// ---------------------------------------------------------------------------
// prep_bond_k: per 16-atom tile emit fp16 image 192x136 (26112 elem = 52224B)
// + fp32 filter logits for 3 layers (shfl-reduce over 16 lanes of a row).
// grid 1024 x 256.
// ---------------------------------------------------------------------------
__global__ void __launch_bounds__(256) prep_bond_k(
    const float* __restrict__ bond, const float* __restrict__ filt_w) {
    __shared__ float sfw[384];
    for (int t = threadIdx.x; t < 384; t += 256) {
        int l = t >> 7, q = t & 127;
        sfw[t] = filt_w[l * 256 + 128 + q];
    }
    __syncthreads();
    size_t tile = blockIdx.x;
    const float* src = bond + tile * 192 * 128;
    __half* dh = g_BB + tile * 26112;
    for (int i = threadIdx.x; i < 192 * 16; i += 256) {
        int row = i >> 4, q = i & 15;
        const float* s = src + row * 128 + q * 8;
        float4 v0 = *(const float4*)s;
        float4 v1 = *(const float4*)(s + 4);
        float v[8] = {v0.x, v0.y, v0.z, v0.w, v1.x, v1.y, v1.z, v1.w};
        unsigned hu[4];
#pragma unroll
        for (int p = 0; p < 4; p++) {
            __half2 hh;
            hh.x = __float2half(v[2 * p]);
            hh.y = __float2half(v[2 * p + 1]);
            hu[p] = reinterpret_cast<unsigned&>(hh);
        }
        *(uint4*)(dh + row * 136 + q * 8) =
            make_uint4(hu[0], hu[1], hu[2], hu[3]);
        // filter logits (exact fp32)
        float p0 = 0.f, p1 = 0.f, p2 = 0.f;
#pragma unroll
        for (int p = 0; p < 8; p++) {
            float vv = v[p];
            p0 += vv * sfw[q * 8 + p];
            p1 += vv * sfw[128 + q * 8 + p];
            p2 += vv * sfw[256 + q * 8 + p];
        }
#pragma unroll
        for (int off = 8; off; off >>= 1) {
            p0 += __shfl_xor_sync(0xFFFFFFFFu, p0, off);
            p1 += __shfl_xor_sync(0xFFFFFFFFu, p1, off);
            p2 += __shfl_xor_sync(0xFFFFFFFFu, p2, off);
        }
        if ((threadIdx.x & 15) == 0) {
            size_t gr = tile * 192 + row;
            g_FL[0][gr] = p0;
            g_FL[1][gr] = p1;
            g_FL[2][gr] = p2;
        }
    }
}

// ---------------------------------------------------------------------------
// proj8 (vectorized): 8 rows of x (smem, stride 68) -> Y1/Y2/S1/S2 buffer yb
// ---------------------------------------------------------------------------
__device__ __forceinline__ void proj8(const float* __restrict__ xs, int bn0,
                                      int r0, int c2, int yb,
                                      const float* __restrict__ cwn,
                                      const float* __restrict__ fwn) {
    const float* wp;
    int st;
    if (c2 < 64) {
        wp = cwn + c2;
        st = 64;
    } else if (c2 < 128) {
        wp = cwn + 64 * 64 + (c2 - 64);
        st = 64;
    } else {
        wp = fwn + (c2 - 128) * 64;
        st = 1;
    }
    float acc[8] = {0.f, 0.f, 0.f, 0.f, 0.f, 0.f, 0.f, 0.f};
#pragma unroll 2
    for (int k = 0; k < 64; k += 4) {
        float4 xv[8];
#pragma unroll
        for (int rr = 0; rr < 8; rr++)
            xv[rr] = *(const float4*)(xs + (r0 + rr) * 68 + k);
#pragma unroll
        for (int j = 0; j < 4; j++) {
            float wv = __ldg(wp + (k + j) * st);
#pragma unroll
            for (int rr = 0; rr < 8; rr++)
                acc[rr] += ((const float*)&xv[rr])[j] * wv;
        }
    }
    if (c2 < 64) {
#pragma unroll
        for (int rr = 0; rr < 8; rr++)
            g_Y1[yb][(bn0 + r0 + rr) * 64 + c2] = acc[rr];
    } else if (c2 < 128) {
#pragma unroll
        for (int rr = 0; rr < 8; rr++)
            g_Y2[yb][(bn0 + r0 + rr) * 64 + (c2 - 64)] = acc[rr];
    } else if (c2 == 128) {
#pragma unroll
        for (int rr = 0; rr < 8; rr++) g_S1[yb][bn0 + r0 + rr] = acc[rr];
    } else {
#pragma unroll
        for (int rr = 0; rr < 8; rr++) g_S2[yb][bn0 + r0 + rr] = acc[rr];
    }
}

__global__ void __launch_bounds__(256) embed_proj_k(
    const int* __restrict__ types, const float* __restrict__ emb,
    const float* __restrict__ cwn, const float* __restrict__ fwn) {
    __shared__ float xs[16 * 68];
    int tid = threadIdx.x;
    int bn0 = blockIdx.x * 16;
    {
        int r = tid >> 4, q = tid & 15;
        int t = types[bn0 + r];
        float4 v = *(const float4*)(emb + t * 64 + q * 4);
        *(float4*)(xs + r * 68 + q * 4) = v;
        *(float4*)(g_X0 + (bn0 + r) * 64 + q * 4) = v;
    }
    __syncthreads();
    if (tid < 130) {
        proj8(xs, bn0, 0, tid, 0, cwn, fwn);
        proj8(xs, bn0, 8, tid, 0, cwn, fwn);
    }
}

// ---------------------------------------------------------------------------
// conv_k: one block = 8 atoms (96 rows), 256 threads, 3 blocks/SM.
// 8 warps = 2 row-groups (48) x 4 col-groups (16).
// Pre-GEMM (overlaps TMA): nb, ft from g_FL+S1+S2, softmax.
// GEMM: ONE pass, per fragment: mma vs Wh and Wl (both accumulate).
// smem (bytes): 16 mbar | 1024 sB(26112) | 27136 sW(32768: hi|lo) |
// 59904 ft(384) | 60288 nb(384) | 60672 xb(2176) | 62848 pb(1280) |
// 64128 y1s(2048) -> 66176
// reuse after GEMM: y2s = sB region, Cs = sW region.
// ---------------------------------------------------------------------------
#define CONV_SMEM 66176

__global__ void __launch_bounds__(256, 3) conv_k(
    int l, int flip, int yrd, int ywr, const int* __restrict__ nbrl,
    const float* __restrict__ cb, const float* __restrict__ fb,
    const float* __restrict__ bag, const float* __restrict__ bab,
    const float* __restrict__ bbg, const float* __restrict__ bbb, int do_proj,
    const float* __restrict__ cwn, const float* __restrict__ fwn) {
    extern __shared__ char smem[];
    unsigned sbase = (unsigned)__cvta_generic_to_shared(smem);
    float* ft = (float*)(smem + 59904);
    int* nb = (int*)(smem + 60288);
    float* xb = (float*)(smem + 60672);
    float* pb = (float*)(smem + 62848);
    float* y1s = (float*)(smem + 64128);
    float* y2s = (float*)(smem + 1024);    // reuse sB after GEMM
    float* Cs = (float*)(smem + 27136);    // reuse sW after GEMM
    unsigned mb0 = sbase + 16;

    const float* Xc = flip ? g_X1 : g_X0;
    float* Xn = flip ? g_X0 : g_X1;
    const float* Y1r = g_Y1[yrd];
    const float* Y2r = g_Y2[yrd];
    const float* S1r = g_S1[yrd];
    const float* S2r = g_S2[yrd];

    int tid = threadIdx.x;
    int lane = tid & 31, w = tid >> 5;
    int bn0 = blockIdx.x * 8;          // 8 atoms per block
    int b = bn0 >> 10;

    if (tid == 0) {
        mbar_init(mb0, 1);
        mbar_expect(mb0, 26112 + 32768);
    }
    __syncthreads();

    size_t tile = blockIdx.x >> 1;
    unsigned half = blockIdx.x & 1;
    const char* bh = (const char*)(g_BB + tile * 26112) + half * 26112;

    if (tid == 0) {
        bulk_cp(sbase + 1024, bh, 26112, mb0);
    } else if (tid == 1) {
        bulk_cp(sbase + 27136, (const char*)&g_WA[l][0], 32768, mb0);
    } else if (tid >= 192) {
        int c = tid - 192;
        pb[c] = cb[c];
        pb[64 + c] = bag[c];
        pb[128 + c] = bab[c];
        pb[192 + c] = bbg[c];
        pb[256 + c] = bbb[c];
    }

    // ---- pre-GEMM: nb + ft (precomputed logits) — overlaps TMA ----
    if (tid < 96) {
        int row = tid;
        int a_ = row / 12, m = row - a_ * 12;
        int nbr = nbrl[(bn0 + a_) * 12 + m];
        nb[row] = nbr;
        ft[row] = __ldg(&g_FL[l][(size_t)blockIdx.x * 96 + row]) +
                  S1r[bn0 + a_] + S2r[b * 1024 + nbr] + fb[0];
    }
    __syncthreads();
    if (tid < 8) {   // softmax over m (folds the 1/12 mean)
        int base = tid * 12;
        float mx = -1e30f;
#pragma unroll
        for (int m = 0; m < 12; m++) mx = fmaxf(mx, ft[base + m]);
        float s = 0.f;
#pragma unroll
        for (int m = 0; m < 12; m++) s += expf(ft[base + m] - mx);
        float inv = 1.f / (12.f * s);
#pragma unroll
        for (int m = 0; m < 12; m++)
            ft[base + m] = expf(ft[base + m] - mx) * inv;
    }

    // ---- GEMM: single pass, bond_h x (Wh + Wl) ----
    int wm = w & 1, wn = w >> 1;
    unsigned laneoff = ((lane & 15) * 136 + (lane >> 4) * 8) * 2;
    const uint2* WH = (const uint2*)(smem + 27136);
    const uint2* WL = (const uint2*)(smem + 27136 + 16384);
    float d[3][2][4];
#pragma unroll
    for (int mt = 0; mt < 3; mt++)
#pragma unroll
        for (int nt = 0; nt < 2; nt++)
#pragma unroll
            for (int fr = 0; fr < 4; fr++) d[mt][nt][fr] = 0.f;

    mbar_wait(mb0);
    {
        unsigned abase = sbase + 1024 + laneoff + (unsigned)(wm * 48 * 272);
#pragma unroll
        for (int ks = 0; ks < 8; ks++) {
            unsigned bfrH[2][2], bfrL[2][2];
#pragma unroll
            for (int nt = 0; nt < 2; nt++) {
                uint2 vH = WH[(ks * 8 + wn * 2 + nt) * 32 + lane];
                uint2 vL = WL[(ks * 8 + wn * 2 + nt) * 32 + lane];
                bfrH[nt][0] = vH.x;
                bfrH[nt][1] = vH.y;
                bfrL[nt][0] = vL.x;
                bfrL[nt][1] = vL.y;
            }
#pragma unroll
            for (int mt = 0; mt < 3; mt++) {
                unsigned afr[4];
                ldmx4(afr, abase + mt * (16 * 272) + ks * 32);
                mma16816(d[mt][0], afr, bfrH[0]);
                mma16816(d[mt][0], afr, bfrL[0]);
                mma16816(d[mt][1], afr, bfrH[1]);
                mma16816(d[mt][1], afr, bfrL[1]);
            }
        }
    }
    __syncthreads();   // all GEMM reads of sB/sW done

    // ---- stage y1/y2 (coalesced) into reused smem ----
    for (int i = tid; i < 1536; i += 256) {
        int row = i >> 4, q = i & 15;
        *(float4*)(y2s + row * 64 + q * 4) =
            *(const float4*)(Y2r + (b * 1024 + nb[row]) * 64 + q * 4);
    }
    if (tid < 128) {
        int a = tid >> 4, q = tid & 15;
        *(float4*)(y1s + a * 64 + q * 4) =
            *(const float4*)(Y1r + (bn0 + a) * 64 + q * 4);
    }
    __syncthreads();

    // ---- epilogue: frag + y1 + y2 + cb -> BN -> relu -> Cs ----
#pragma unroll
    for (int mt = 0; mt < 3; mt++) {
        int r0 = wm * 48 + mt * 16 + (lane >> 2);
#pragma unroll
        for (int nt = 0; nt < 2; nt++) {
            int c0 = wn * 16 + nt * 8 + (lane & 3) * 2;
#pragma unroll
            for (int fr = 0; fr < 4; fr++) {
                int row = r0 + (fr >> 1) * 8;
                int c = c0 + (fr & 1);
                int a_ = row / 12;
                float v = d[mt][nt][fr] + y1s[a_ * 64 + c] +
                          y2s[row * 64 + c] + pb[c];
                v = fmaxf(pb[64 + c] * (v * BN_ALPHA) + pb[128 + c], 0.f);
                Cs[row * 65 + c] = v;
            }
        }
    }
    __syncthreads();

    // ---- weighted mean, BN, residual relu; stash xn ----
#pragma unroll
    for (int q = 0; q < 2; q++) {
        int idx = tid + 256 * q;   // < 512 = 8*64
        int a_ = idx >> 6, c = idx & 63;
        float s = 0.f;
#pragma unroll
        for (int m = 0; m < 12; m++)
            s += ft[a_ * 12 + m] * Cs[(a_ * 12 + m) * 65 + c];
        s = pb[192 + c] * (s * BN_ALPHA) + pb[256 + c];
        int gi = (bn0 + a_) * 64 + c;
        float xv = fmaxf(Xc[gi] + s, 0.f);
        Xn[gi] = xv;
        xb[a_ * 68 + c] = xv;
    }
    __syncthreads();

    // ---- fused next-layer projection (8 atoms, write buffer ywr) ----
    if (do_proj && tid < 130) {
        proj8(xb, bn0, 0, tid, ywr, cwn, fwn);
    }
}

// ---------------------------------------------------------------------------
__global__ void __launch_bounds__(256) final_k(const int* __restrict__ tix,
                                               const float* __restrict__ dw,
                                               const float* __restrict__ db,
                                               float* __restrict__ out) {
    __shared__ float cs[64 * 68];
    __shared__ float wd[64 * 65];
    int b = blockIdx.x, tid = threadIdx.x;
    for (int t = tid; t < 4096; t += 256) {
        int k = t >> 6, f = t & 63;
        wd[k * 65 + f] = dw[t];
    }
    for (int t = tid; t < 1024; t += 256) {
        int j = t >> 4, q = t & 15;
        int ti = tix[b * 64 + j];
        float4 v = *(const float4*)(g_X1 + (b * 1024 + ti) * 64 + q * 4);
        v.x = fmaxf(v.x, 0.f);
        v.y = fmaxf(v.y, 0.f);
        v.z = fmaxf(v.z, 0.f);
        v.w = fmaxf(v.w, 0.f);
        *(float4*)(cs + j * 68 + q * 4) = v;
    }
    __syncthreads();
    for (int t = tid; t < 4096; t += 256) {
        int j = t >> 6, f = t & 63;
        float acc = db[f];
#pragma unroll 8
        for (int k = 0; k < 64; k++) acc += cs[j * 68 + k] * wd[k * 65 + f];
        out[b * 4096 + t] = fmaxf(acc, 0.f);
    }
}

// ---------------------------------------------------------------------------
extern "C" void kernel_launch(void* const* d_in, const int* in_sizes, int n_in,
                              void* d_out, int out_size) {
    const int* atom_types = (const int*)d_in[0];
    const float* bond = (const float*)d_in[1];
    const int* nbrl = (const int*)d_in[2];
    const int* tix = (const int*)d_in[3];
    const float* emb = (const float*)d_in[4];
    const float* core_w = (const float*)d_in[5];
    const float* core_b = (const float*)d_in[6];
    const float* filt_w = (const float*)d_in[7];
    const float* filt_b = (const float*)d_in[8];
    const float* bna_g = (const float*)d_in[9];
    const float* bna_b = (const float*)d_in[10];
    const float* bnb_g = (const float*)d_in[11];
    const float* bnb_b = (const float*)d_in[12];
    const float* dw = (const float*)d_in[13];
    const float* db = (const float*)d_in[14];
    float* out = (float*)d_out;

    cudaFuncSetAttribute(conv_k, cudaFuncAttributeMaxDynamicSharedMemorySize,
                         CONV_SMEM);

    prep_w_k<<<3, 256>>>(core_w);
    prep_bond_k<<<1024, 256>>>(bond, filt_w);
    embed_proj_k<<<1024, 256>>>(atom_types, emb, core_w, filt_w);
    for (int l = 0; l < 3; l++) {
        int flip = l & 1;
        int yrd = l & 1;
        int ywr = (l + 1) & 1;
        int do_proj = (l < 2) ? 1 : 0;
        const float* cwn = core_w + (l + 1 < 3 ? (l + 1) : l) * 256 * 64;
        const float* fwn = filt_w + (l + 1 < 3 ? (l + 1) : l) * 256;
        conv_k<<<2048, 256, CONV_SMEM>>>(
            l, flip, yrd, ywr, nbrl, core_b + l * 64, filt_b + l,
            bna_g + l * 64, bna_b + l * 64, bnb_g + l * 64, bnb_b + l * 64,
            do_proj, cwn, fwn);
    }
    final_k<<<16, 256>>>(tix, dw, db, out);
}

// round 14
// speedup vs baseline: 2.6396x; 1.1899x over previous
#include <cuda_runtime.h>
#include <cuda_fp16.h>

// ---------------------------------------------------------------------------
// CGCNN: B=16, N=1024, M=12, F=64, BF=128, N_CONV=3, VOCAB=100
// total@W = x@W1 + gather(x@W2) + bond@W3 ; proj fused into conv/embed.
// R14: full fp16 GEMM (bond_h @ W_h, err ~1e-4 total), Cs staged fp16,
// fused ys = y1+y2 staging, 4 blocks/SM, proj tail parallelized 2x.
// Filter logits exact fp32 via g_FL.
// ---------------------------------------------------------------------------

#define BN_ALPHA 0.99950037f   // 1/sqrt(1+1e-3)

__device__ float g_X0[16 * 1024 * 64];
__device__ float g_X1[16 * 1024 * 64];
__device__ float g_Y1[2][16 * 1024 * 64];
__device__ float g_Y2[2][16 * 1024 * 64];
__device__ float g_S1[2][16 * 1024];
__device__ float g_S2[2][16 * 1024];
__device__ float g_FL[3][16 * 1024 * 12];         // bond @ fw3 (fp32, exact)
__device__ __half g_WA[3][8192];                  // W frag-order fp16
__device__ __half g_BB[1024ull * 192 * 136];      // bond fp16 blobs, 52KB/tile

// ---- mbarrier / bulk helpers ----------------------------------------------
__device__ __forceinline__ void mbar_init(unsigned m, unsigned c) {
    asm volatile("mbarrier.init.shared.b64 [%0], %1;" ::"r"(m), "r"(c)
                 : "memory");
}
__device__ __forceinline__ void mbar_expect(unsigned m, unsigned b) {
    asm volatile("mbarrier.arrive.expect_tx.shared.b64 _, [%0], %1;" ::"r"(m),
                 "r"(b)
                 : "memory");
}
__device__ __forceinline__ void mbar_wait(unsigned m) {
    asm volatile(
        "{\n\t.reg .pred P;\n\tW%=:\n\t"
        "mbarrier.try_wait.parity.acquire.cta.shared::cta.b64 P, [%0], 0;\n\t"
        "@!P bra W%=;\n\t}" ::"r"(m)
        : "memory");
}
__device__ __forceinline__ void bulk_cp(unsigned d, const void* s, unsigned b,
                                        unsigned m) {
    asm volatile(
        "cp.async.bulk.shared::cta.global.mbarrier::complete_tx::bytes "
        "[%0], [%1], %2, [%3];" ::"r"(d),
        "l"(s), "r"(b), "r"(m)
        : "memory");
}

// ---- tensor-core helpers (sm_80+ PTX) -------------------------------------
__device__ __forceinline__ void mma16816(float* d, const unsigned* a,
                                         const unsigned* b) {
    asm volatile(
        "mma.sync.aligned.m16n8k16.row.col.f32.f16.f16.f32 "
        "{%0,%1,%2,%3}, {%4,%5,%6,%7}, {%8,%9}, {%0,%1,%2,%3};"
        : "+f"(d[0]), "+f"(d[1]), "+f"(d[2]), "+f"(d[3])
        : "r"(a[0]), "r"(a[1]), "r"(a[2]), "r"(a[3]), "r"(b[0]), "r"(b[1]));
}
__device__ __forceinline__ void ldmx4(unsigned* a, unsigned addr) {
    asm volatile(
        "ldmatrix.sync.aligned.m8n8.x4.shared.b16 {%0,%1,%2,%3}, [%4];"
        : "=r"(a[0]), "=r"(a[1]), "=r"(a[2]), "=r"(a[3])
        : "r"(addr));
}

// ---------------------------------------------------------------------------
// prep_w_k: W fp16 in mma B-fragment order.
// word t (half2): r=t&1, lane=(t>>1)&31, nt=(t>>6)&1, wn=(t>>7)&3, ks=t>>9;
// n = wn*16+nt*8+(lane>>2); k = ks*16+(lane&3)*2+r*8. grid 3 x 256.
// ---------------------------------------------------------------------------
__global__ void __launch_bounds__(256) prep_w_k(const float* __restrict__ cw) {
    int l = blockIdx.x;
    const float* W = cw + l * 256 * 64 + 128 * 64;   // [k][n]
    __half2* outp = (__half2*)g_WA[l];
    for (int t = threadIdx.x; t < 4096; t += 256) {
        int r = t & 1;
        int lane = (t >> 1) & 31;
        int nt = (t >> 6) & 1, wn = (t >> 7) & 3, ks = t >> 9;
        int n = wn * 16 + nt * 8 + (lane >> 2);
        int k = ks * 16 + (lane & 3) * 2 + r * 8;
        __half2 hh;
        hh.x = __float2half(W[k * 64 + n]);
        hh.y = __float2half(W[(k + 1) * 64 + n]);
        outp[t] = hh;
    }
}

// ---------------------------------------------------------------------------
// prep_bond_k: per 16-atom tile emit fp16 image 192x136 + fp32 filter
// logits for 3 layers (shfl-reduce over 16 lanes of a row). grid 1024 x 256.
// ---------------------------------------------------------------------------
__global__ void __launch_bounds__(256) prep_bond_k(
    const float* __restrict__ bond, const float* __restrict__ filt_w) {
    __shared__ float sfw[384];
    for (int t = threadIdx.x; t < 384; t += 256) {
        int l = t >> 7, q = t & 127;
        sfw[t] = filt_w[l * 256 + 128 + q];
    }
    __syncthreads();
    size_t tile = blockIdx.x;
    const float* src = bond + tile * 192 * 128;
    __half* dh = g_BB + tile * 26112;
    for (int i = threadIdx.x; i < 192 * 16; i += 256) {
        int row = i >> 4, q = i & 15;
        const float* s = src + row * 128 + q * 8;
        float4 v0 = *(const float4*)s;
        float4 v1 = *(const float4*)(s + 4);
        float v[8] = {v0.x, v0.y, v0.z, v0.w, v1.x, v1.y, v1.z, v1.w};
        unsigned hu[4];
#pragma unroll
        for (int p = 0; p < 4; p++) {
            __half2 hh;
            hh.x = __float2half(v[2 * p]);
            hh.y = __float2half(v[2 * p + 1]);
            hu[p] = reinterpret_cast<unsigned&>(hh);
        }
        *(uint4*)(dh + row * 136 + q * 8) =
            make_uint4(hu[0], hu[1], hu[2], hu[3]);
        float p0 = 0.f, p1 = 0.f, p2 = 0.f;
#pragma unroll
        for (int p = 0; p < 8; p++) {
            float vv = v[p];
            p0 += vv * sfw[q * 8 + p];
            p1 += vv * sfw[128 + q * 8 + p];
            p2 += vv * sfw[256 + q * 8 + p];
        }
#pragma unroll
        for (int off = 8; off; off >>= 1) {
            p0 += __shfl_xor_sync(0xFFFFFFFFu, p0, off);
            p1 += __shfl_xor_sync(0xFFFFFFFFu, p1, off);
            p2 += __shfl_xor_sync(0xFFFFFFFFu, p2, off);
        }
        if ((threadIdx.x & 15) == 0) {
            size_t gr = tile * 192 + row;
            g_FL[0][gr] = p0;
            g_FL[1][gr] = p1;
            g_FL[2][gr] = p2;
        }
    }
}

// ---------------------------------------------------------------------------
// proj4: 4 rows of x (smem, stride 68) -> Y1/Y2/S1/S2 buffer yb
// ---------------------------------------------------------------------------
__device__ __forceinline__ void proj4(const float* __restrict__ xs, int bn0,
                                      int r0, int c2, int yb,
                                      const float* __restrict__ cwn,
                                      const float* __restrict__ fwn) {
    const float* wp;
    int st;
    if (c2 < 64) {
        wp = cwn + c2;
        st = 64;
    } else if (c2 < 128) {
        wp = cwn + 64 * 64 + (c2 - 64);
        st = 64;
    } else {
        wp = fwn + (c2 - 128) * 64;
        st = 1;
    }
    float acc[4] = {0.f, 0.f, 0.f, 0.f};
#pragma unroll 2
    for (int k = 0; k < 64; k += 4) {
        float4 xv[4];
#pragma unroll
        for (int rr = 0; rr < 4; rr++)
            xv[rr] = *(const float4*)(xs + (r0 + rr) * 68 + k);
#pragma unroll
        for (int j = 0; j < 4; j++) {
            float wv = __ldg(wp + (k + j) * st);
#pragma unroll
            for (int rr = 0; rr < 4; rr++)
                acc[rr] += ((const float*)&xv[rr])[j] * wv;
        }
    }
    if (c2 < 64) {
#pragma unroll
        for (int rr = 0; rr < 4; rr++)
            g_Y1[yb][(bn0 + r0 + rr) * 64 + c2] = acc[rr];
    } else if (c2 < 128) {
#pragma unroll
        for (int rr = 0; rr < 4; rr++)
            g_Y2[yb][(bn0 + r0 + rr) * 64 + (c2 - 64)] = acc[rr];
    } else if (c2 == 128) {
#pragma unroll
        for (int rr = 0; rr < 4; rr++) g_S1[yb][bn0 + r0 + rr] = acc[rr];
    } else {
#pragma unroll
        for (int rr = 0; rr < 4; rr++) g_S2[yb][bn0 + r0 + rr] = acc[rr];
    }
}

__global__ void __launch_bounds__(256) embed_proj_k(
    const int* __restrict__ types, const float* __restrict__ emb,
    const float* __restrict__ cwn, const float* __restrict__ fwn) {
    __shared__ float xs[16 * 68];
    int tid = threadIdx.x;
    int bn0 = blockIdx.x * 16;
    {
        int r = tid >> 4, q = tid & 15;
        int t = types[bn0 + r];
        float4 v = *(const float4*)(emb + t * 64 + q * 4);
        *(float4*)(xs + r * 68 + q * 4) = v;
        *(float4*)(g_X0 + (bn0 + r) * 64 + q * 4) = v;
    }
    __syncthreads();
    // 520 items: 130 c2 x 4 row-quads
    for (int it = tid; it < 520; it += 256) {
        int c2 = it % 130, rh = it / 130;
        proj4(xs, bn0, rh * 4, c2, 0, cwn, fwn);
    }
}

// ---------------------------------------------------------------------------
// conv_k: one block = 8 atoms (96 rows), 256 threads, 4 blocks/SM.
// 8 warps = 2 row-groups (48) x 4 col-groups (16); 48 mma/warp (pure fp16).
// smem (bytes): 16 mbar | 1024 sB(26112) | 27136 sW(16384) | 43520 ft(384) |
// 43904 nb(384) | 44288 xb(2176) | 46464 pb(1280) -> 47744
// reuse after GEMM: ys(fp32 96x64 = 24576) = sB region;
//                   CsH(fp16 96x68 = 13056) = sW region.
// ---------------------------------------------------------------------------
#define CONV_SMEM 47744

__global__ void __launch_bounds__(256, 4) conv_k(
    int l, int flip, int yrd, int ywr, const int* __restrict__ nbrl,
    const float* __restrict__ cb, const float* __restrict__ fb,
    const float* __restrict__ bag, const float* __restrict__ bab,
    const float* __restrict__ bbg, const float* __restrict__ bbb, int do_proj,
    const float* __restrict__ cwn, const float* __restrict__ fwn) {
    extern __shared__ char smem[];
    unsigned sbase = (unsigned)__cvta_generic_to_shared(smem);
    float* ft = (float*)(smem + 43520);
    int* nb = (int*)(smem + 43904);
    float* xb = (float*)(smem + 44288);
    float* pb = (float*)(smem + 46464);
    float* ys = (float*)(smem + 1024);      // reuse sB after GEMM
    __half* CsH = (__half*)(smem + 27136);  // reuse sW after GEMM
    unsigned mb0 = sbase + 16;

    const float* Xc = flip ? g_X1 : g_X0;
    float* Xn = flip ? g_X0 : g_X1;
    const float* Y1r = g_Y1[yrd];
    const float* Y2r = g_Y2[yrd];
    const float* S1r = g_S1[yrd];
    const float* S2r = g_S2[yrd];

    int tid = threadIdx.x;
    int lane = tid & 31, w = tid >> 5;
    int bn0 = blockIdx.x * 8;          // 8 atoms per block
    int b = bn0 >> 10;

    if (tid == 0) {
        mbar_init(mb0, 1);
        mbar_expect(mb0, 26112 + 16384);
    }
    __syncthreads();

    size_t tile = blockIdx.x >> 1;
    unsigned half = blockIdx.x & 1;
    const char* bh = (const char*)(g_BB + tile * 26112) + half * 26112;

    if (tid == 0) {
        bulk_cp(sbase + 1024, bh, 26112, mb0);
    } else if (tid == 1) {
        bulk_cp(sbase + 27136, (const char*)&g_WA[l][0], 16384, mb0);
    } else if (tid >= 192) {
        int c = tid - 192;
        pb[c] = cb[c];
        pb[64 + c] = bag[c];
        pb[128 + c] = bab[c];
        pb[192 + c] = bbg[c];
        pb[256 + c] = bbb[c];
    }

    // ---- pre-GEMM: nb + ft (precomputed logits) — overlaps TMA ----
    if (tid < 96) {
        int row = tid;
        int a_ = row / 12, m = row - a_ * 12;
        int nbr = nbrl[(bn0 + a_) * 12 + m];
        nb[row] = nbr;
        ft[row] = __ldg(&g_FL[l][(size_t)blockIdx.x * 96 + row]) +
                  S1r[bn0 + a_] + S2r[b * 1024 + nbr] + fb[0];
    }
    __syncthreads();
    if (tid < 8) {   // softmax over m (folds the 1/12 mean)
        int base = tid * 12;
        float mx = -1e30f;
#pragma unroll
        for (int m = 0; m < 12; m++) mx = fmaxf(mx, ft[base + m]);
        float s = 0.f;
#pragma unroll
        for (int m = 0; m < 12; m++) s += expf(ft[base + m] - mx);
        float inv = 1.f / (12.f * s);
#pragma unroll
        for (int m = 0; m < 12; m++)
            ft[base + m] = expf(ft[base + m] - mx) * inv;
    }

    // ---- GEMM: bond_h @ W_h (pure fp16, one pass, 48 mma/warp) ----
    int wm = w & 1, wn = w >> 1;
    unsigned laneoff = ((lane & 15) * 136 + (lane >> 4) * 8) * 2;
    const uint2* WH = (const uint2*)(smem + 27136);
    float d[3][2][4];
#pragma unroll
    for (int mt = 0; mt < 3; mt++)
#pragma unroll
        for (int nt = 0; nt < 2; nt++)
#pragma unroll
            for (int fr = 0; fr < 4; fr++) d[mt][nt][fr] = 0.f;

    mbar_wait(mb0);
    {
        unsigned abase = sbase + 1024 + laneoff + (unsigned)(wm * 48 * 272);
#pragma unroll
        for (int ks = 0; ks < 8; ks++) {
            unsigned bfr[2][2];
#pragma unroll
            for (int nt = 0; nt < 2; nt++) {
                uint2 vH = WH[(ks * 8 + wn * 2 + nt) * 32 + lane];
                bfr[nt][0] = vH.x;
                bfr[nt][1] = vH.y;
            }
#pragma unroll
            for (int mt = 0; mt < 3; mt++) {
                unsigned afr[4];
                ldmx4(afr, abase + mt * (16 * 272) + ks * 32);
                mma16816(d[mt][0], afr, bfr[0]);
                mma16816(d[mt][1], afr, bfr[1]);
            }
        }
    }
    __syncthreads();   // all GEMM reads of sB/sW done

    // ---- stage ys = y1[atom] + y2[nbr] (coalesced, y1 L1-cached) ----
    for (int i = tid; i < 1536; i += 256) {
        int row = i >> 4, q = i & 15;
        int a_ = row / 12;
        float4 v2 = *(const float4*)(Y2r + (b * 1024 + nb[row]) * 64 + q * 4);
        float4 v1 = *(const float4*)(Y1r + (bn0 + a_) * 64 + q * 4);
        v2.x += v1.x;
        v2.y += v1.y;
        v2.z += v1.z;
        v2.w += v1.w;
        *(float4*)(ys + row * 64 + q * 4) = v2;
    }
    __syncthreads();

    // ---- epilogue: frag + ys + cb -> BN -> relu -> CsH (fp16) ----
#pragma unroll
    for (int mt = 0; mt < 3; mt++) {
        int rbase = wm * 48 + mt * 16 + (lane >> 2);
#pragma unroll
        for (int nt = 0; nt < 2; nt++) {
            int c0 = wn * 16 + nt * 8 + (lane & 3) * 2;
            float ga = pb[64 + c0], gb_ = pb[64 + c0 + 1];
            float ba = pb[128 + c0], bb_ = pb[128 + c0 + 1];
            float cba = pb[c0], cbb = pb[c0 + 1];
#pragma unroll
            for (int h = 0; h < 2; h++) {
                int row = rbase + h * 8;
                float2 yv = *(const float2*)(ys + row * 64 + c0);
                float v0 = d[mt][nt][2 * h] + yv.x + cba;
                float v1 = d[mt][nt][2 * h + 1] + yv.y + cbb;
                v0 = fmaxf(ga * (v0 * BN_ALPHA) + ba, 0.f);
                v1 = fmaxf(gb_ * (v1 * BN_ALPHA) + bb_, 0.f);
                __half2 hv;
                hv.x = __float2half(v0);
                hv.y = __float2half(v1);
                *(__half2*)(CsH + row * 68 + c0) = hv;
            }
        }
    }
    __syncthreads();

    // ---- weighted mean, BN, residual relu; stash xn ----
#pragma unroll
    for (int q = 0; q < 2; q++) {
        int idx = tid + 256 * q;   // < 512 = 8*64
        int a_ = idx >> 6, c = idx & 63;
        float s = 0.f;
#pragma unroll
        for (int m = 0; m < 12; m++)
            s += ft[a_ * 12 + m] * __half2float(CsH[(a_ * 12 + m) * 68 + c]);
        s = pb[192 + c] * (s * BN_ALPHA) + pb[256 + c];
        int gi = (bn0 + a_) * 64 + c;
        float xv = fmaxf(Xc[gi] + s, 0.f);
        Xn[gi] = xv;
        xb[a_ * 68 + c] = xv;
    }
    __syncthreads();

    // ---- fused next-layer projection: 260 items (130 c2 x 2 row-quads) ----
    if (do_proj) {
        for (int it = tid; it < 260; it += 256) {
            int c2 = it % 130, rh = it / 130;
            proj4(xb, bn0, rh * 4, c2, ywr, cwn, fwn);
        }
    }
}

// ---------------------------------------------------------------------------
__global__ void __launch_bounds__(256) final_k(const int* __restrict__ tix,
                                               const float* __restrict__ dw,
                                               const float* __restrict__ db,
                                               float* __restrict__ out) {
    __shared__ float cs[64 * 68];
    __shared__ float wd[64 * 65];
    int b = blockIdx.x, tid = threadIdx.x;
    for (int t = tid; t < 4096; t += 256) {
        int k = t >> 6, f = t & 63;
        wd[k * 65 + f] = dw[t];
    }
    for (int t = tid; t < 1024; t += 256) {
        int j = t >> 4, q = t & 15;
        int ti = tix[b * 64 + j];
        float4 v = *(const float4*)(g_X1 + (b * 1024 + ti) * 64 + q * 4);
        v.x = fmaxf(v.x, 0.f);
        v.y = fmaxf(v.y, 0.f);
        v.z = fmaxf(v.z, 0.f);
        v.w = fmaxf(v.w, 0.f);
        *(float4*)(cs + j * 68 + q * 4) = v;
    }
    __syncthreads();
    for (int t = tid; t < 4096; t += 256) {
        int j = t >> 6, f = t & 63;
        float acc = db[f];
#pragma unroll 8
        for (int k = 0; k < 64; k++) acc += cs[j * 68 + k] * wd[k * 65 + f];
        out[b * 4096 + t] = fmaxf(acc, 0.f);
    }
}

// ---------------------------------------------------------------------------
extern "C" void kernel_launch(void* const* d_in, const int* in_sizes, int n_in,
                              void* d_out, int out_size) {
    const int* atom_types = (const int*)d_in[0];
    const float* bond = (const float*)d_in[1];
    const int* nbrl = (const int*)d_in[2];
    const int* tix = (const int*)d_in[3];
    const float* emb = (const float*)d_in[4];
    const float* core_w = (const float*)d_in[5];
    const float* core_b = (const float*)d_in[6];
    const float* filt_w = (const float*)d_in[7];
    const float* filt_b = (const float*)d_in[8];
    const float* bna_g = (const float*)d_in[9];
    const float* bna_b = (const float*)d_in[10];
    const float* bnb_g = (const float*)d_in[11];
    const float* bnb_b = (const float*)d_in[12];
    const float* dw = (const float*)d_in[13];
    const float* db = (const float*)d_in[14];
    float* out = (float*)d_out;

    cudaFuncSetAttribute(conv_k, cudaFuncAttributeMaxDynamicSharedMemorySize,
                         CONV_SMEM);

    prep_w_k<<<3, 256>>>(core_w);
    prep_bond_k<<<1024, 256>>>(bond, filt_w);
    embed_proj_k<<<1024, 256>>>(atom_types, emb, core_w, filt_w);
    for (int l = 0; l < 3; l++) {
        int flip = l & 1;
        int yrd = l & 1;
        int ywr = (l + 1) & 1;
        int do_proj = (l < 2) ? 1 : 0;
        const float* cwn = core_w + (l + 1 < 3 ? (l + 1) : l) * 256 * 64;
        const float* fwn = filt_w + (l + 1 < 3 ? (l + 1) : l) * 256;
        conv_k<<<2048, 256, CONV_SMEM>>>(
            l, flip, yrd, ywr, nbrl, core_b + l * 64, filt_b + l,
            bna_g + l * 64, bna_b + l * 64, bnb_g + l * 64, bnb_b + l * 64,
            do_proj, cwn, fwn);
    }
    final_k<<<16, 256>>>(tix, dw, db, out);
}

// round 15
// speedup vs baseline: 2.8360x; 1.0744x over previous
#include <cuda_runtime.h>
#include <cuda_fp16.h>

// ---------------------------------------------------------------------------
// CGCNN: B=16, N=1024, M=12, F=64, BF=128, N_CONV=3, VOCAB=100
// total@W = x@W1 + gather(x@W2) + bond@W3 ; proj fused into conv/prep.
// R15: merged prep kernel (bond fp16 + logits + embed + proj0 + W prep);
// conv epilogue reads y2 direct (no ys staging phase), half2 weighted mean.
// GEMM: bond_h @ W_h fp16 (rel_err ~1e-4, 10x under threshold).
// ---------------------------------------------------------------------------

#define BN_ALPHA 0.99950037f   // 1/sqrt(1+1e-3)

__device__ float g_X0[16 * 1024 * 64];
__device__ float g_X1[16 * 1024 * 64];
__device__ float g_Y1[2][16 * 1024 * 64];
__device__ float g_Y2[2][16 * 1024 * 64];
__device__ float g_S1[2][16 * 1024];
__device__ float g_S2[2][16 * 1024];
__device__ float g_FL[3][16 * 1024 * 12];         // bond @ fw3 (fp32, exact)
__device__ __half g_WA[3][8192];                  // W frag-order fp16
__device__ __half g_BB[1024ull * 192 * 136];      // bond fp16 blobs, 52KB/tile

// ---- mbarrier / bulk helpers ----------------------------------------------
__device__ __forceinline__ void mbar_init(unsigned m, unsigned c) {
    asm volatile("mbarrier.init.shared.b64 [%0], %1;" ::"r"(m), "r"(c)
                 : "memory");
}
__device__ __forceinline__ void mbar_expect(unsigned m, unsigned b) {
    asm volatile("mbarrier.arrive.expect_tx.shared.b64 _, [%0], %1;" ::"r"(m),
                 "r"(b)
                 : "memory");
}
__device__ __forceinline__ void mbar_wait(unsigned m) {
    asm volatile(
        "{\n\t.reg .pred P;\n\tW%=:\n\t"
        "mbarrier.try_wait.parity.acquire.cta.shared::cta.b64 P, [%0], 0;\n\t"
        "@!P bra W%=;\n\t}" ::"r"(m)
        : "memory");
}
__device__ __forceinline__ void bulk_cp(unsigned d, const void* s, unsigned b,
                                        unsigned m) {
    asm volatile(
        "cp.async.bulk.shared::cta.global.mbarrier::complete_tx::bytes "
        "[%0], [%1], %2, [%3];" ::"r"(d),
        "l"(s), "r"(b), "r"(m)
        : "memory");
}

// ---- tensor-core helpers (sm_80+ PTX) -------------------------------------
__device__ __forceinline__ void mma16816(float* d, const unsigned* a,
                                         const unsigned* b) {
    asm volatile(
        "mma.sync.aligned.m16n8k16.row.col.f32.f16.f16.f32 "
        "{%0,%1,%2,%3}, {%4,%5,%6,%7}, {%8,%9}, {%0,%1,%2,%3};"
        : "+f"(d[0]), "+f"(d[1]), "+f"(d[2]), "+f"(d[3])
        : "r"(a[0]), "r"(a[1]), "r"(a[2]), "r"(a[3]), "r"(b[0]), "r"(b[1]));
}
__device__ __forceinline__ void ldmx4(unsigned* a, unsigned addr) {
    asm volatile(
        "ldmatrix.sync.aligned.m8n8.x4.shared.b16 {%0,%1,%2,%3}, [%4];"
        : "=r"(a[0]), "=r"(a[1]), "=r"(a[2]), "=r"(a[3])
        : "r"(addr));
}

// ---------------------------------------------------------------------------
// proj4: 4 rows of x (smem, stride 68) -> Y1/Y2/S1/S2 buffer yb
// ---------------------------------------------------------------------------
__device__ __forceinline__ void proj4(const float* __restrict__ xs, int bn0,
                                      int r0, int c2, int yb,
                                      const float* __restrict__ cwn,
                                      const float* __restrict__ fwn) {
    const float* wp;
    int st;
    if (c2 < 64) {
        wp = cwn + c2;
        st = 64;
    } else if (c2 < 128) {
        wp = cwn + 64 * 64 + (c2 - 64);
        st = 64;
    } else {
        wp = fwn + (c2 - 128) * 64;
        st = 1;
    }
    float acc[4] = {0.f, 0.f, 0.f, 0.f};
#pragma unroll 2
    for (int k = 0; k < 64; k += 4) {
        float4 xv[4];
#pragma unroll
        for (int rr = 0; rr < 4; rr++)
            xv[rr] = *(const float4*)(xs + (r0 + rr) * 68 + k);
#pragma unroll
        for (int j = 0; j < 4; j++) {
            float wv = __ldg(wp + (k + j) * st);
#pragma unroll
            for (int rr = 0; rr < 4; rr++)
                acc[rr] += ((const float*)&xv[rr])[j] * wv;
        }
    }
    if (c2 < 64) {
#pragma unroll
        for (int rr = 0; rr < 4; rr++)
            g_Y1[yb][(bn0 + r0 + rr) * 64 + c2] = acc[rr];
    } else if (c2 < 128) {
#pragma unroll
        for (int rr = 0; rr < 4; rr++)
            g_Y2[yb][(bn0 + r0 + rr) * 64 + (c2 - 64)] = acc[rr];
    } else if (c2 == 128) {
#pragma unroll
        for (int rr = 0; rr < 4; rr++) g_S1[yb][bn0 + r0 + rr] = acc[rr];
    } else {
#pragma unroll
        for (int rr = 0; rr < 4; rr++) g_S2[yb][bn0 + r0 + rr] = acc[rr];
    }
}

// ---------------------------------------------------------------------------
// prep_k (merged): per 16-atom tile —
//  (a) bond fp16 image 192x136 + exact fp32 filter logits (3 layers),
//  (b) embedding gather + layer-0 projection (Y/S buffer 0),
//  (c) blocks 0-2: W fp16 fragment-order prep for layer blockIdx.x.
// grid 1024 x 256.
// ---------------------------------------------------------------------------
__global__ void __launch_bounds__(256) prep_k(
    const float* __restrict__ bond, const float* __restrict__ filt_w,
    const int* __restrict__ types, const float* __restrict__ emb,
    const float* __restrict__ core_w) {
    __shared__ float sfw[384];
    __shared__ float xs[16 * 68];
    int tid = threadIdx.x;
    size_t tile = blockIdx.x;
    int bn0 = blockIdx.x * 16;

    for (int t = tid; t < 384; t += 256) {
        int l = t >> 7, q = t & 127;
        sfw[t] = filt_w[l * 256 + 128 + q];
    }
    {   // embed: 16 atoms x 16 float4
        int r = tid >> 4, q = tid & 15;
        int ty = types[bn0 + r];
        float4 v = *(const float4*)(emb + ty * 64 + q * 4);
        *(float4*)(xs + r * 68 + q * 4) = v;
        *(float4*)(g_X0 + (bn0 + r) * 64 + q * 4) = v;
    }
    __syncthreads();

    // (a) bond conversion + logits
    const float* src = bond + tile * 192 * 128;
    __half* dh = g_BB + tile * 26112;
    for (int i = tid; i < 192 * 16; i += 256) {
        int row = i >> 4, q = i & 15;
        const float* s = src + row * 128 + q * 8;
        float4 v0 = *(const float4*)s;
        float4 v1 = *(const float4*)(s + 4);
        float v[8] = {v0.x, v0.y, v0.z, v0.w, v1.x, v1.y, v1.z, v1.w};
        unsigned hu[4];
#pragma unroll
        for (int p = 0; p < 4; p++) {
            __half2 hh;
            hh.x = __float2half(v[2 * p]);
            hh.y = __float2half(v[2 * p + 1]);
            hu[p] = reinterpret_cast<unsigned&>(hh);
        }
        *(uint4*)(dh + row * 136 + q * 8) =
            make_uint4(hu[0], hu[1], hu[2], hu[3]);
        float p0 = 0.f, p1 = 0.f, p2 = 0.f;
#pragma unroll
        for (int p = 0; p < 8; p++) {
            float vv = v[p];
            p0 += vv * sfw[q * 8 + p];
            p1 += vv * sfw[128 + q * 8 + p];
            p2 += vv * sfw[256 + q * 8 + p];
        }
#pragma unroll
        for (int off = 8; off; off >>= 1) {
            p0 += __shfl_xor_sync(0xFFFFFFFFu, p0, off);
            p1 += __shfl_xor_sync(0xFFFFFFFFu, p1, off);
            p2 += __shfl_xor_sync(0xFFFFFFFFu, p2, off);
        }
        if ((tid & 15) == 0) {
            size_t gr = tile * 192 + row;
            g_FL[0][gr] = p0;
            g_FL[1][gr] = p1;
            g_FL[2][gr] = p2;
        }
    }

    // (b) layer-0 projection: 520 items = 130 c2 x 4 row-quads
    for (int it = tid; it < 520; it += 256) {
        int c2 = it % 130, rh = it / 130;
        proj4(xs, bn0, rh * 4, c2, 0, core_w, filt_w);
    }

    // (c) W prep for 3 layers
    if (blockIdx.x < 3) {
        int l = blockIdx.x;
        const float* W = core_w + l * 256 * 64 + 128 * 64;   // [k][n]
        __half2* outp = (__half2*)g_WA[l];
        for (int t = tid; t < 4096; t += 256) {
            int r = t & 1;
            int lane = (t >> 1) & 31;
            int nt = (t >> 6) & 1, wn = (t >> 7) & 3, ks = t >> 9;
            int n = wn * 16 + nt * 8 + (lane >> 2);
            int k = ks * 16 + (lane & 3) * 2 + r * 8;
            __half2 hh;
            hh.x = __float2half(W[k * 64 + n]);
            hh.y = __float2half(W[(k + 1) * 64 + n]);
            outp[t] = hh;
        }
    }
}

// ---------------------------------------------------------------------------
// conv_k: one block = 8 atoms (96 rows), 256 threads, 4 blocks/SM.
// 8 warps = 2 row-groups (48) x 4 col-groups (16); 48 mma/warp.
// smem (bytes): 16 mbar | 1024 sB(26112) | 27136 sW(16384) | 43520 ft(384) |
// 43904 nb(384) | 44288 xb(2176) | 46464 pb(1280) | 47744 y1s(2048) -> 49792
// reuse after GEMM: CsH(fp16 96x68) = sW region.
// ---------------------------------------------------------------------------
#define CONV_SMEM 49792

__global__ void __launch_bounds__(256, 4) conv_k(
    int l, int flip, int yrd, int ywr, const int* __restrict__ nbrl,
    const float* __restrict__ cb, const float* __restrict__ fb,
    const float* __restrict__ bag, const float* __restrict__ bab,
    const float* __restrict__ bbg, const float* __restrict__ bbb, int do_proj,
    const float* __restrict__ cwn, const float* __restrict__ fwn) {
    extern __shared__ char smem[];
    unsigned sbase = (unsigned)__cvta_generic_to_shared(smem);
    float* ft = (float*)(smem + 43520);
    int* nb = (int*)(smem + 43904);
    float* xb = (float*)(smem + 44288);
    float* pb = (float*)(smem + 46464);
    float* y1s = (float*)(smem + 47744);
    __half* CsH = (__half*)(smem + 27136);  // reuse sW after GEMM
    unsigned mb0 = sbase + 16;

    const float* Xc = flip ? g_X1 : g_X0;
    float* Xn = flip ? g_X0 : g_X1;
    const float* Y1r = g_Y1[yrd];
    const float* Y2r = g_Y2[yrd];
    const float* S1r = g_S1[yrd];
    const float* S2r = g_S2[yrd];

    int tid = threadIdx.x;
    int lane = tid & 31, w = tid >> 5;
    int bn0 = blockIdx.x * 8;          // 8 atoms per block
    int b = bn0 >> 10;

    if (tid == 0) {
        mbar_init(mb0, 1);
        mbar_expect(mb0, 26112 + 16384);
    }
    __syncthreads();

    size_t tile = blockIdx.x >> 1;
    unsigned half = blockIdx.x & 1;
    const char* bh = (const char*)(g_BB + tile * 26112) + half * 26112;

    if (tid == 0) {
        bulk_cp(sbase + 1024, bh, 26112, mb0);
    } else if (tid == 1) {
        bulk_cp(sbase + 27136, (const char*)&g_WA[l][0], 16384, mb0);
    } else if (tid >= 2 && tid < 98) {
        // pre-GEMM: nb + ft (precomputed fp32 logits) — overlaps TMA
        int row = tid - 2;
        int a_ = row / 12, m = row - a_ * 12;
        int nbr = nbrl[(bn0 + a_) * 12 + m];
        nb[row] = nbr;
        ft[row] = __ldg(&g_FL[l][(size_t)blockIdx.x * 96 + row]) +
                  S1r[bn0 + a_] + S2r[b * 1024 + nbr] + fb[0];
    }
    if (tid >= 128) {
        // y1 stage (8 atoms x 16 quads) — overlaps TMA
        int a = (tid - 128) >> 4, q = tid & 15;
        *(float4*)(y1s + a * 64 + q * 4) =
            *(const float4*)(Y1r + (bn0 + a) * 64 + q * 4);
    }
    if (tid >= 192) {
        int c = tid - 192;
        pb[c] = cb[c];
        pb[64 + c] = bag[c];
        pb[128 + c] = bab[c];
        pb[192 + c] = bbg[c];
        pb[256 + c] = bbb[c];
    }
    __syncthreads();
    if (tid < 8) {   // softmax over m (folds the 1/12 mean)
        int base = tid * 12;
        float mx = -1e30f;
#pragma unroll
        for (int m = 0; m < 12; m++) mx = fmaxf(mx, ft[base + m]);
        float s = 0.f;
#pragma unroll
        for (int m = 0; m < 12; m++) s += expf(ft[base + m] - mx);
        float inv = 1.f / (12.f * s);
#pragma unroll
        for (int m = 0; m < 12; m++)
            ft[base + m] = expf(ft[base + m] - mx) * inv;
    }

    // ---- GEMM: bond_h @ W_h (fp16, 48 mma/warp) ----
    int wm = w & 1, wn = w >> 1;
    unsigned laneoff = ((lane & 15) * 136 + (lane >> 4) * 8) * 2;
    const uint2* WH = (const uint2*)(smem + 27136);
    float d[3][2][4];
#pragma unroll
    for (int mt = 0; mt < 3; mt++)
#pragma unroll
        for (int nt = 0; nt < 2; nt++)
#pragma unroll
            for (int fr = 0; fr < 4; fr++) d[mt][nt][fr] = 0.f;

    mbar_wait(mb0);
    {
        unsigned abase = sbase + 1024 + laneoff + (unsigned)(wm * 48 * 272);
#pragma unroll
        for (int ks = 0; ks < 8; ks++) {
            unsigned bfr[2][2];
#pragma unroll
            for (int nt = 0; nt < 2; nt++) {
                uint2 vH = WH[(ks * 8 + wn * 2 + nt) * 32 + lane];
                bfr[nt][0] = vH.x;
                bfr[nt][1] = vH.y;
            }
#pragma unroll
            for (int mt = 0; mt < 3; mt++) {
                unsigned afr[4];
                ldmx4(afr, abase + mt * (16 * 272) + ks * 32);
                mma16816(d[mt][0], afr, bfr[0]);
                mma16816(d[mt][1], afr, bfr[1]);
            }
        }
    }
    __syncthreads();   // all warps done reading sW -> CsH may overwrite

    // ---- epilogue: frag + y1s + y2(direct LDG) + cb -> BN -> relu -> CsH
#pragma unroll
    for (int mt = 0; mt < 3; mt++) {
        int rbase = wm * 48 + mt * 16 + (lane >> 2);
#pragma unroll
        for (int nt = 0; nt < 2; nt++) {
            int c0 = wn * 16 + nt * 8 + (lane & 3) * 2;
            float ga = pb[64 + c0], gb_ = pb[64 + c0 + 1];
            float ba = pb[128 + c0], bb_ = pb[128 + c0 + 1];
            float cba = pb[c0], cbb = pb[c0 + 1];
#pragma unroll
            for (int h = 0; h < 2; h++) {
                int row = rbase + h * 8;
                int a_ = row / 12;
                int nbr = nb[row];
                float2 y2v =
                    *(const float2*)(Y2r + (b * 1024 + nbr) * 64 + c0);
                float2 y1v = *(const float2*)(y1s + a_ * 64 + c0);
                float v0 = d[mt][nt][2 * h] + y1v.x + y2v.x + cba;
                float v1 = d[mt][nt][2 * h + 1] + y1v.y + y2v.y + cbb;
                v0 = fmaxf(ga * (v0 * BN_ALPHA) + ba, 0.f);
                v1 = fmaxf(gb_ * (v1 * BN_ALPHA) + bb_, 0.f);
                __half2 hv;
                hv.x = __float2half(v0);
                hv.y = __float2half(v1);
                *(__half2*)(CsH + row * 68 + c0) = hv;
            }
        }
    }
    __syncthreads();

    // ---- weighted mean (half2 single pass), BN, residual relu; stash xn ----
    {
        int a_ = tid >> 5;         // 8 atoms
        int c = (tid & 31) * 2;    // col pair
        float s0 = 0.f, s1 = 0.f;
#pragma unroll
        for (int m = 0; m < 12; m++) {
            float wgt = ft[a_ * 12 + m];
            __half2 hv = *(const __half2*)(CsH + (a_ * 12 + m) * 68 + c);
            float2 fv = __half22float2(hv);
            s0 += wgt * fv.x;
            s1 += wgt * fv.y;
        }
        s0 = pb[192 + c] * (s0 * BN_ALPHA) + pb[256 + c];
        s1 = pb[192 + c + 1] * (s1 * BN_ALPHA) + pb[256 + c + 1];
        int gi = (bn0 + a_) * 64 + c;
        float2 xc = *(const float2*)(Xc + gi);
        float xv0 = fmaxf(xc.x + s0, 0.f);
        float xv1 = fmaxf(xc.y + s1, 0.f);
        *(float2*)(Xn + gi) = make_float2(xv0, xv1);
        xb[a_ * 68 + c] = xv0;
        xb[a_ * 68 + c + 1] = xv1;
    }
    __syncthreads();

    // ---- fused next-layer projection: 260 items (130 c2 x 2 row-quads) ----
    if (do_proj) {
        for (int it = tid; it < 260; it += 256) {
            int c2 = it % 130, rh = it / 130;
            proj4(xb, bn0, rh * 4, c2, ywr, cwn, fwn);
        }
    }
}

// ---------------------------------------------------------------------------
__global__ void __launch_bounds__(256) final_k(const int* __restrict__ tix,
                                               const float* __restrict__ dw,
                                               const float* __restrict__ db,
                                               float* __restrict__ out) {
    __shared__ float cs[64 * 68];
    __shared__ float wd[64 * 65];
    int b = blockIdx.x, tid = threadIdx.x;
    for (int t = tid; t < 4096; t += 256) {
        int k = t >> 6, f = t & 63;
        wd[k * 65 + f] = dw[t];
    }
    for (int t = tid; t < 1024; t += 256) {
        int j = t >> 4, q = t & 15;
        int ti = tix[b * 64 + j];
        float4 v = *(const float4*)(g_X1 + (b * 1024 + ti) * 64 + q * 4);
        v.x = fmaxf(v.x, 0.f);
        v.y = fmaxf(v.y, 0.f);
        v.z = fmaxf(v.z, 0.f);
        v.w = fmaxf(v.w, 0.f);
        *(float4*)(cs + j * 68 + q * 4) = v;
    }
    __syncthreads();
    for (int t = tid; t < 4096; t += 256) {
        int j = t >> 6, f = t & 63;
        float acc = db[f];
#pragma unroll 8
        for (int k = 0; k < 64; k++) acc += cs[j * 68 + k] * wd[k * 65 + f];
        out[b * 4096 + t] = fmaxf(acc, 0.f);
    }
}

// ---------------------------------------------------------------------------
extern "C" void kernel_launch(void* const* d_in, const int* in_sizes, int n_in,
                              void* d_out, int out_size) {
    const int* atom_types = (const int*)d_in[0];
    const float* bond = (const float*)d_in[1];
    const int* nbrl = (const int*)d_in[2];
    const int* tix = (const int*)d_in[3];
    const float* emb = (const float*)d_in[4];
    const float* core_w = (const float*)d_in[5];
    const float* core_b = (const float*)d_in[6];
    const float* filt_w = (const float*)d_in[7];
    const float* filt_b = (const float*)d_in[8];
    const float* bna_g = (const float*)d_in[9];
    const float* bna_b = (const float*)d_in[10];
    const float* bnb_g = (const float*)d_in[11];
    const float* bnb_b = (const float*)d_in[12];
    const float* dw = (const float*)d_in[13];
    const float* db = (const float*)d_in[14];
    float* out = (float*)d_out;

    cudaFuncSetAttribute(conv_k, cudaFuncAttributeMaxDynamicSharedMemorySize,
                         CONV_SMEM);

    prep_k<<<1024, 256>>>(bond, filt_w, atom_types, emb, core_w);
    for (int l = 0; l < 3; l++) {
        int flip = l & 1;
        int yrd = l & 1;
        int ywr = (l + 1) & 1;
        int do_proj = (l < 2) ? 1 : 0;
        const float* cwn = core_w + (l + 1 < 3 ? (l + 1) : l) * 256 * 64;
        const float* fwn = filt_w + (l + 1 < 3 ? (l + 1) : l) * 256;
        conv_k<<<2048, 256, CONV_SMEM>>>(
            l, flip, yrd, ywr, nbrl, core_b + l * 64, filt_b + l,
            bna_g + l * 64, bna_b + l * 64, bnb_g + l * 64, bnb_b + l * 64,
            do_proj, cwn, fwn);
    }
    final_k<<<16, 256>>>(tix, dw, db, out);
}